// round 4
// baseline (speedup 1.0000x reference)
#include <cuda_runtime.h>
#include <math.h>

// Problem constants
#define BB   64
#define TT   512
#define EE   300
#define HDIM 256
#define G4   1024    // 4*HDIM
#define KTAG 20
#define GRID_P 128
#define CLU  8       // cluster size (k-slices of one (dir, batch-tile))

typedef unsigned long long ull;

// ---------------- scratch (device globals; no runtime allocation) ----------------
__device__ float g_X[(size_t)2 * BB * TT * G4];     // input-gate preactivations (+bias)
__device__ float g_h[(size_t)2 * BB * TT * HDIM];   // hidden states per step
__device__ float g_emis[(size_t)BB * TT * KTAG];    // emissions

// ---------------- packed fp32x2 helpers ----------------
__device__ __forceinline__ ull ffma2(ull a, ull b, ull c) {
    ull d;
    asm("fma.rn.f32x2 %0, %1, %2, %3;" : "=l"(d) : "l"(a), "l"(b), "l"(c));
    return d;
}
__device__ __forceinline__ ull f2u2(float x, float y) {
    ull v;
    asm("mov.b64 %0, {%1, %2};" : "=l"(v) : "f"(x), "f"(y));
    return v;
}
__device__ __forceinline__ float2 u2f2(ull v) {
    float2 f;
    asm("mov.b64 {%0, %1}, %2;" : "=f"(f.x), "=f"(f.y) : "l"(v));
    return f;
}
__device__ __forceinline__ unsigned smem_u32(const void* p) {
    unsigned a;
    asm("{ .reg .u64 t; cvta.to.shared.u64 t, %1; cvt.u32.u64 %0, t; }" : "=r"(a) : "l"(p));
    return a;
}
__device__ __forceinline__ unsigned mapa_rank(unsigned addr, unsigned rank) {
    unsigned r;
    asm("mapa.shared::cluster.u32 %0, %1, %2;" : "=r"(r) : "r"(addr), "r"(rank));
    return r;
}
__device__ __forceinline__ void st_cluster_f32(unsigned addr, float v) {
    asm volatile("st.shared::cluster.f32 [%0], %1;" :: "r"(addr), "f"(v) : "memory");
}

// =====================================================================
// Kernel 1: fused embedding gather + input-gate GEMM (+bias), both dirs
// =====================================================================
#define BM 128
#define BN 64
#define BK 16

__global__ void gates_gemm_kernel(const int* __restrict__ sentence,
                                  const int* __restrict__ lengths,
                                  const float* __restrict__ emb,
                                  const float* __restrict__ Wf_ih,
                                  const float* __restrict__ bf,
                                  const float* __restrict__ Wb_ih,
                                  const float* __restrict__ bb)
{
    const int dir = blockIdx.z;
    const int m0  = blockIdx.x * BM;
    const int n0  = blockIdx.y * BN;
    const float* __restrict__ W    = dir ? Wb_ih : Wf_ih;
    const float* __restrict__ bias = dir ? bb    : bf;

    __shared__ float As[BK][BM + 4];
    __shared__ float Bs[BK][BN + 4];
    __shared__ int   tok[BM];

    const int tid = threadIdx.x;
    const int b   = m0 / TT;

    if (tid < BM) {
        int t = (m0 + tid) % TT;
        if (dir) {
            int len = lengths[b];
            t = (t < len) ? (len - 1 - t) : t;
        }
        tok[tid] = sentence[b * TT + t];
    }
    __syncthreads();

    ull acc[4][4];
#pragma unroll
    for (int i = 0; i < 4; i++)
#pragma unroll
        for (int j = 0; j < 4; j++) acc[i][j] = 0ull;

    const int tx = tid & 15;
    const int ty = tid >> 4;

    for (int k0 = 0; k0 < 304; k0 += BK) {
        {
            const int ar = tid >> 1;
            const int ac = (tid & 1) * 8;
            const float* erow = emb + (size_t)tok[ar] * EE;
#pragma unroll
            for (int i = 0; i < 8; i++) {
                int k = k0 + ac + i;
                As[ac + i][ar] = (k < EE) ? erow[k] : 0.f;
            }
        }
        {
            const int bn = tid >> 2;
            const int bk = (tid & 3) * 4;
            const float* wrow = W + (size_t)(n0 + bn) * EE;
#pragma unroll
            for (int i = 0; i < 4; i++) {
                int k = k0 + bk + i;
                Bs[bk + i][bn] = (k < EE) ? wrow[k] : 0.f;
            }
        }
        __syncthreads();

#pragma unroll
        for (int kk = 0; kk < BK; kk++) {
            ulonglong2 a0 = *(const ulonglong2*)&As[kk][ty * 8];
            ulonglong2 a1 = *(const ulonglong2*)&As[kk][ty * 8 + 4];
            float4 bv = *(const float4*)&Bs[kk][tx * 4];
            ull b0 = f2u2(bv.x, bv.x);
            ull b1 = f2u2(bv.y, bv.y);
            ull b2 = f2u2(bv.z, bv.z);
            ull b3 = f2u2(bv.w, bv.w);
            acc[0][0] = ffma2(a0.x, b0, acc[0][0]);
            acc[0][1] = ffma2(a0.x, b1, acc[0][1]);
            acc[0][2] = ffma2(a0.x, b2, acc[0][2]);
            acc[0][3] = ffma2(a0.x, b3, acc[0][3]);
            acc[1][0] = ffma2(a0.y, b0, acc[1][0]);
            acc[1][1] = ffma2(a0.y, b1, acc[1][1]);
            acc[1][2] = ffma2(a0.y, b2, acc[1][2]);
            acc[1][3] = ffma2(a0.y, b3, acc[1][3]);
            acc[2][0] = ffma2(a1.x, b0, acc[2][0]);
            acc[2][1] = ffma2(a1.x, b1, acc[2][1]);
            acc[2][2] = ffma2(a1.x, b2, acc[2][2]);
            acc[2][3] = ffma2(a1.x, b3, acc[2][3]);
            acc[3][0] = ffma2(a1.y, b0, acc[3][0]);
            acc[3][1] = ffma2(a1.y, b1, acc[3][1]);
            acc[3][2] = ffma2(a1.y, b2, acc[3][2]);
            acc[3][3] = ffma2(a1.y, b3, acc[3][3]);
        }
        __syncthreads();
    }

    float4 bv;
    bv.x = bias[n0 + tx * 4 + 0];
    bv.y = bias[n0 + tx * 4 + 1];
    bv.z = bias[n0 + tx * 4 + 2];
    bv.w = bias[n0 + tx * 4 + 3];
#pragma unroll
    for (int mp = 0; mp < 4; mp++) {
        float2 c0 = u2f2(acc[mp][0]);
        float2 c1 = u2f2(acc[mp][1]);
        float2 c2 = u2f2(acc[mp][2]);
        float2 c3 = u2f2(acc[mp][3]);
        size_t mA = (size_t)m0 + ty * 8 + 2 * mp;
        float4 vA, vB;
        vA.x = c0.x + bv.x; vA.y = c1.x + bv.y; vA.z = c2.x + bv.z; vA.w = c3.x + bv.w;
        vB.x = c0.y + bv.x; vB.y = c1.y + bv.y; vB.z = c2.y + bv.z; vB.w = c3.y + bv.w;
        *(float4*)&g_X[((size_t)dir * BB * TT + mA)     * G4 + n0 + tx * 4] = vA;
        *(float4*)&g_X[((size_t)dir * BB * TT + mA + 1) * G4 + n0 + tx * 4] = vB;
    }
}

// =====================================================================
// Kernel 2: PERSISTENT cluster LSTM.
// Cluster of 8 CTAs = 8 k-slices of one (dir, batch-tile). h exchanged
// via DSMEM (st.shared::cluster) into a double-buffered smem tile; one
// barrier.cluster per step. No gmem round trip, no gpu fences.
// blockIdx.x = ks + 8*(dir + 2*bt); cluster rank == ks.
// =====================================================================
#define WS_STRIDE 264
#define HS_STRIDE 260
#define HS_BUF (8 * HS_STRIDE)
#define SMEM_LSTM ((4 * 32 * WS_STRIDE + 2 * HS_BUF) * 4)

__device__ __forceinline__ float sigf(float x) { return 1.f / (1.f + expf(-x)); }

__global__ void __cluster_dims__(CLU, 1, 1)
lstm_persistent_kernel(const float* __restrict__ Wf_hh,
                       const float* __restrict__ Wb_hh)
{
    extern __shared__ float sm[];
    float* Ws  = sm;                       // [4*32][WS_STRIDE]
    float* hsm = sm + 4 * 32 * WS_STRIDE;  // [2][8][HS_STRIDE]

    const int bx  = blockIdx.x;
    const int ks  = bx & 7;                // == cluster rank
    const int dir = (bx >> 3) & 1;
    const int bt  = bx >> 4;
    const int k0  = ks * 32;
    const int b0  = bt * 8;
    const int tid = threadIdx.x;
    const float* __restrict__ W = dir ? Wb_hh : Wf_hh;

    // cooperative load of W slice into smem (once)
    for (int i = tid; i < 128 * 64; i += 256) {
        int r = i >> 6;
        int c = (i & 63) * 4;
        int gate = r >> 5, k_l = r & 31;
        float4 v = *(const float4*)(W + ((size_t)(gate * 256 + k0 + k_l)) * HDIM + c);
        *(float4*)(Ws + (size_t)r * WS_STRIDE + c) = v;
    }
    // zero buffer 0 only (h(-1) = 0); buffer 1 is fully overwritten at t=0
    for (int i = tid; i < HS_BUF; i += 256) hsm[i] = 0.f;

    const int b_l = tid & 7, k_l = tid >> 3;
    const int b = b0 + b_l, k = k0 + k_l;
    const float* wi = Ws + (size_t)(0 * 32 + k_l) * WS_STRIDE;
    const float* wf = Ws + (size_t)(1 * 32 + k_l) * WS_STRIDE;
    const float* wg = Ws + (size_t)(2 * 32 + k_l) * WS_STRIDE;
    const float* wo = Ws + (size_t)(3 * 32 + k_l) * WS_STRIDE;
    const float* xbase = g_X + (((size_t)dir * BB + b) * TT) * G4 + k;
    float*       houtb = g_h + (((size_t)dir * BB + b) * TT) * HDIM + k;

    // remote (cluster) addresses of hsm base for each rank
    const unsigned hsm_u = smem_u32(hsm);
    const unsigned woff  = (unsigned)(b_l * HS_STRIDE + k) * 4u;  // byte offset of my value in a buffer
    unsigned raddr[CLU];
#pragma unroll
    for (int r = 0; r < CLU; r++) raddr[r] = mapa_rank(hsm_u, (unsigned)r) + woff;

    // init barrier: smem init + peer smem validity
    asm volatile("barrier.cluster.arrive.aligned;" ::: "memory");
    asm volatile("barrier.cluster.wait.aligned;" ::: "memory");

    float c_st = 0.f;
    float xi = xbase[0], xf = xbase[256], xg = xbase[512], xo = xbase[768];

    int cur = 0;
    for (int t = 0; t < TT; t++) {
        const float* hr = hsm + cur * HS_BUF + b_l * HS_STRIDE;

        ulonglong2 ai, af, ag, ao;
        ai.x = ai.y = af.x = af.y = 0ull;
        ag.x = ag.y = ao.x = ao.y = 0ull;

#pragma unroll 4
        for (int kk = 0; kk < HDIM; kk += 8) {
            ulonglong2 h0 = *(const ulonglong2*)(hr + kk);
            ulonglong2 h1 = *(const ulonglong2*)(hr + kk + 4);
            ulonglong2 w;
            w = *(const ulonglong2*)(wi + kk);     ai.x = ffma2(h0.x, w.x, ai.x); ai.y = ffma2(h0.y, w.y, ai.y);
            w = *(const ulonglong2*)(wi + kk + 4); ai.x = ffma2(h1.x, w.x, ai.x); ai.y = ffma2(h1.y, w.y, ai.y);
            w = *(const ulonglong2*)(wf + kk);     af.x = ffma2(h0.x, w.x, af.x); af.y = ffma2(h0.y, w.y, af.y);
            w = *(const ulonglong2*)(wf + kk + 4); af.x = ffma2(h1.x, w.x, af.x); af.y = ffma2(h1.y, w.y, af.y);
            w = *(const ulonglong2*)(wg + kk);     ag.x = ffma2(h0.x, w.x, ag.x); ag.y = ffma2(h0.y, w.y, ag.y);
            w = *(const ulonglong2*)(wg + kk + 4); ag.x = ffma2(h1.x, w.x, ag.x); ag.y = ffma2(h1.y, w.y, ag.y);
            w = *(const ulonglong2*)(wo + kk);     ao.x = ffma2(h0.x, w.x, ao.x); ao.y = ffma2(h0.y, w.y, ao.y);
            w = *(const ulonglong2*)(wo + kk + 4); ao.x = ffma2(h1.x, w.x, ao.x); ao.y = ffma2(h1.y, w.y, ao.y);
        }

        float2 s0, s1;
        s0 = u2f2(ai.x); s1 = u2f2(ai.y);
        float gi = xi + s0.x + s0.y + s1.x + s1.y;
        s0 = u2f2(af.x); s1 = u2f2(af.y);
        float gf = xf + s0.x + s0.y + s1.x + s1.y;
        s0 = u2f2(ag.x); s1 = u2f2(ag.y);
        float gg = xg + s0.x + s0.y + s1.x + s1.y;
        s0 = u2f2(ao.x); s1 = u2f2(ao.y);
        float go = xo + s0.x + s0.y + s1.x + s1.y;

        // prefetch X(t+1): drains under the exchange + barrier
        if (t + 1 < TT) {
            const float* xr = xbase + (size_t)(t + 1) * G4;
            xi = xr[0]; xf = xr[256]; xg = xr[512]; xo = xr[768];
        }

        c_st = sigf(gf) * c_st + sigf(gi) * tanhf(gg);
        float hn = sigf(go) * tanhf(c_st);
        houtb[(size_t)t * HDIM] = hn;   // archival store for emissions (off critical path)

        if (t + 1 < TT) {
            const unsigned nxt_off = (unsigned)((cur ^ 1) * HS_BUF) * 4u;
#pragma unroll
            for (int r = 0; r < CLU; r++) st_cluster_f32(raddr[r] + nxt_off, hn);
            asm volatile("barrier.cluster.arrive.aligned;" ::: "memory");
            asm volatile("barrier.cluster.wait.aligned;" ::: "memory");
            cur ^= 1;
        }
    }
}

// =====================================================================
// Kernel 3: emissions (W_out cached in smem)
// =====================================================================
__global__ void emis_kernel(const int* __restrict__ lengths,
                            const float* __restrict__ W_out,
                            const float* __restrict__ b_out)
{
    __shared__ float Wsm[KTAG * 2 * HDIM];
    __shared__ float bsm[KTAG];

    const int tid = threadIdx.x;
    for (int i = tid; i < KTAG * 2 * HDIM; i += 256) Wsm[i] = W_out[i];
    if (tid < KTAG) bsm[tid] = b_out[tid];
    __syncthreads();

    const int warp = tid >> 5;
    const int lane = tid & 31;
    const int r = blockIdx.x * 8 + warp;
    const int b = r >> 9;
    const int t = r & 511;
    const int len = lengths[b];
    const int tr  = (t < len) ? (len - 1 - t) : t;

    const float* hf = g_h + (((size_t)0 * BB + b) * TT + t)  * HDIM;
    const float* hb = g_h + (((size_t)1 * BB + b) * TT + tr) * HDIM;

    float x[16];
#pragma unroll
    for (int i = 0; i < 8; i++) x[i]     = hf[lane + 32 * i];
#pragma unroll
    for (int i = 0; i < 8; i++) x[8 + i] = hb[lane + 32 * i];

    for (int kk = 0; kk < KTAG; kk++) {
        const float* w = Wsm + (size_t)kk * (2 * HDIM);
        float s = 0.f;
#pragma unroll
        for (int i = 0; i < 8; i++) s += x[i]     * w[lane + 32 * i];
#pragma unroll
        for (int i = 0; i < 8; i++) s += x[8 + i] * w[HDIM + lane + 32 * i];
#pragma unroll
        for (int off = 16; off; off >>= 1) s += __shfl_xor_sync(0xffffffffu, s, off);
        if (lane == 0) g_emis[((size_t)b * TT + t) * KTAG + kk] = s + bsm[kk];
    }
}

// =====================================================================
// Kernel 4: Viterbi. Emissions in smem; simple compare-select argmax
// (first-max semantics == jnp.argmax).
// =====================================================================
#define VIT_SMEM 53248

__global__ void viterbi_kernel(const int* __restrict__ lengths,
                               const int* __restrict__ stop_id_p,
                               const float* __restrict__ trans,
                               float* __restrict__ out)
{
    extern __shared__ char vsm[];
    float* emis_s = (float*)vsm;                 // TT*KTAG
    float* tr     = emis_s + TT * KTAG;          // KTAG*KTAG
    float* delta  = tr + KTAG * KTAG;            // KTAG
    float* term   = delta + KTAG;                // KTAG
    unsigned char* bp = (unsigned char*)(term + KTAG);

    const int b = blockIdx.x;
    const int lane = threadIdx.x;

    for (int i = lane; i < TT * KTAG; i += 32)
        emis_s[i] = g_emis[(size_t)b * TT * KTAG + i];
    for (int i = lane; i < KTAG * KTAG; i += 32) tr[i] = trans[i];
    if (lane < KTAG) delta[lane] = 0.f;
    __syncwarp();

    const int len  = lengths[b];
    const int stop = *stop_id_p;

    for (int t = 0; t < TT; t++) {
        float nd = 0.f; int bpv = 0;
        if (lane < KTAG) {
            if (t < len) {
                const float* trl = tr + lane * KTAG;
                float best = -3.4e38f; int arg = 0;
#pragma unroll
                for (int p = 0; p < KTAG; p++) {
                    float s = delta[p] + trl[p];
                    if (s > best) { best = s; arg = p; }
                }
                nd  = best + emis_s[t * KTAG + lane];
                bpv = arg;
            } else {
                nd  = delta[lane];
                bpv = lane;
            }
        }
        __syncwarp();
        if (lane < KTAG) { delta[lane] = nd; bp[t * KTAG + lane] = (unsigned char)bpv; }
        __syncwarp();
    }

    if (lane < KTAG) term[lane] = delta[lane] + tr[stop * KTAG + lane];
    __syncwarp();

    if (lane == 0) {
        float best = -3.4e38f; int arg = 0;
        for (int j = 0; j < KTAG; j++)
            if (term[j] > best) { best = term[j]; arg = j; }
        out[b] = best;
        float* po = out + BB + (size_t)b * (TT + 1);
        po[TT] = (float)arg;
        int tag = arg;
        for (int t = TT - 1; t >= 0; t--) {
            tag = bp[t * KTAG + tag];
            po[t] = (float)tag;
        }
    }
}

// =====================================================================
// launch
// =====================================================================
extern "C" void kernel_launch(void* const* d_in, const int* in_sizes, int n_in,
                              void* d_out, int out_size)
{
    (void)in_sizes; (void)n_in; (void)out_size;
    const int*   sentence = (const int*)d_in[0];
    const int*   lengths  = (const int*)d_in[1];
    const int*   stop_id  = (const int*)d_in[3];
    const float* emb      = (const float*)d_in[4];
    const float* Wf_ih    = (const float*)d_in[5];
    const float* Wf_hh    = (const float*)d_in[6];
    const float* bf       = (const float*)d_in[7];
    const float* Wb_ih    = (const float*)d_in[8];
    const float* Wb_hh    = (const float*)d_in[9];
    const float* bb       = (const float*)d_in[10];
    const float* W_out    = (const float*)d_in[11];
    const float* b_out    = (const float*)d_in[12];
    const float* trans    = (const float*)d_in[13];
    float* out = (float*)d_out;

    static int attr_set = 0;
    if (!attr_set) {
        cudaFuncSetAttribute(lstm_persistent_kernel,
                             cudaFuncAttributeMaxDynamicSharedMemorySize, SMEM_LSTM);
        cudaFuncSetAttribute(viterbi_kernel,
                             cudaFuncAttributeMaxDynamicSharedMemorySize, VIT_SMEM);
        attr_set = 1;
    }

    dim3 g1(BB * TT / BM, G4 / BN, 2);
    gates_gemm_kernel<<<g1, 256>>>(sentence, lengths, emb, Wf_ih, bf, Wb_ih, bb);

    lstm_persistent_kernel<<<GRID_P, 256, SMEM_LSTM>>>(Wf_hh, Wb_hh);

    emis_kernel<<<BB * TT / 8, 256>>>(lengths, W_out, b_out);

    viterbi_kernel<<<BB, 32, VIT_SMEM>>>(lengths, stop_id, trans, out);
}

// round 5
// speedup vs baseline: 1.3224x; 1.3224x over previous
#include <cuda_runtime.h>
#include <math.h>

// Problem constants
#define BB   64
#define TT   512
#define EE   300
#define HDIM 256
#define G4   1024    // 4*HDIM
#define KTAG 20
#define GRID_P 128

typedef unsigned long long ull;

// ---------------- scratch (device globals; no runtime allocation) ----------------
__device__ float g_X[(size_t)2 * BB * TT * G4];     // input-gate preactivations (+bias)
__device__ float g_h[(size_t)2 * BB * TT * HDIM];   // hidden states per step
__device__ float g_emis[(size_t)BB * TT * KTAG];    // emissions
__device__ int   g_flagsA[16 * 8 * 32];             // per-(group,ks) monotone flags, 128B apart

// ---------------- packed fp32x2 helpers ----------------
__device__ __forceinline__ ull ffma2(ull a, ull b, ull c) {
    ull d;
    asm("fma.rn.f32x2 %0, %1, %2, %3;" : "=l"(d) : "l"(a), "l"(b), "l"(c));
    return d;
}
__device__ __forceinline__ ull f2u2(float x, float y) {
    ull v;
    asm("mov.b64 %0, {%1, %2};" : "=l"(v) : "f"(x), "f"(y));
    return v;
}
__device__ __forceinline__ float2 u2f2(ull v) {
    float2 f;
    asm("mov.b64 {%0, %1}, %2;" : "=f"(f.x), "=f"(f.y) : "l"(v));
    return f;
}

// =====================================================================
// Kernel 1: fused embedding gather + input-gate GEMM (+bias), both dirs
// =====================================================================
#define BM 128
#define BN 64
#define BK 16

__global__ void gates_gemm_kernel(const int* __restrict__ sentence,
                                  const int* __restrict__ lengths,
                                  const float* __restrict__ emb,
                                  const float* __restrict__ Wf_ih,
                                  const float* __restrict__ bf,
                                  const float* __restrict__ Wb_ih,
                                  const float* __restrict__ bb)
{
    const int dir = blockIdx.z;
    const int m0  = blockIdx.x * BM;
    const int n0  = blockIdx.y * BN;
    const float* __restrict__ W    = dir ? Wb_ih : Wf_ih;
    const float* __restrict__ bias = dir ? bb    : bf;

    __shared__ float As[BK][BM + 4];
    __shared__ float Bs[BK][BN + 4];
    __shared__ int   tok[BM];

    const int tid = threadIdx.x;
    const int b   = m0 / TT;

    if (tid < BM) {
        int t = (m0 + tid) % TT;
        if (dir) {
            int len = lengths[b];
            t = (t < len) ? (len - 1 - t) : t;
        }
        tok[tid] = sentence[b * TT + t];
    }
    __syncthreads();

    ull acc[4][4];
#pragma unroll
    for (int i = 0; i < 4; i++)
#pragma unroll
        for (int j = 0; j < 4; j++) acc[i][j] = 0ull;

    const int tx = tid & 15;
    const int ty = tid >> 4;

    for (int k0 = 0; k0 < 304; k0 += BK) {
        {
            const int ar = tid >> 1;
            const int ac = (tid & 1) * 8;
            const float* erow = emb + (size_t)tok[ar] * EE;
#pragma unroll
            for (int i = 0; i < 8; i++) {
                int k = k0 + ac + i;
                As[ac + i][ar] = (k < EE) ? erow[k] : 0.f;
            }
        }
        {
            const int bn = tid >> 2;
            const int bk = (tid & 3) * 4;
            const float* wrow = W + (size_t)(n0 + bn) * EE;
#pragma unroll
            for (int i = 0; i < 4; i++) {
                int k = k0 + bk + i;
                Bs[bk + i][bn] = (k < EE) ? wrow[k] : 0.f;
            }
        }
        __syncthreads();

#pragma unroll
        for (int kk = 0; kk < BK; kk++) {
            ulonglong2 a0 = *(const ulonglong2*)&As[kk][ty * 8];
            ulonglong2 a1 = *(const ulonglong2*)&As[kk][ty * 8 + 4];
            float4 bv = *(const float4*)&Bs[kk][tx * 4];
            ull b0 = f2u2(bv.x, bv.x);
            ull b1 = f2u2(bv.y, bv.y);
            ull b2 = f2u2(bv.z, bv.z);
            ull b3 = f2u2(bv.w, bv.w);
            acc[0][0] = ffma2(a0.x, b0, acc[0][0]);
            acc[0][1] = ffma2(a0.x, b1, acc[0][1]);
            acc[0][2] = ffma2(a0.x, b2, acc[0][2]);
            acc[0][3] = ffma2(a0.x, b3, acc[0][3]);
            acc[1][0] = ffma2(a0.y, b0, acc[1][0]);
            acc[1][1] = ffma2(a0.y, b1, acc[1][1]);
            acc[1][2] = ffma2(a0.y, b2, acc[1][2]);
            acc[1][3] = ffma2(a0.y, b3, acc[1][3]);
            acc[2][0] = ffma2(a1.x, b0, acc[2][0]);
            acc[2][1] = ffma2(a1.x, b1, acc[2][1]);
            acc[2][2] = ffma2(a1.x, b2, acc[2][2]);
            acc[2][3] = ffma2(a1.x, b3, acc[2][3]);
            acc[3][0] = ffma2(a1.y, b0, acc[3][0]);
            acc[3][1] = ffma2(a1.y, b1, acc[3][1]);
            acc[3][2] = ffma2(a1.y, b2, acc[3][2]);
            acc[3][3] = ffma2(a1.y, b3, acc[3][3]);
        }
        __syncthreads();
    }

    float4 bv;
    bv.x = bias[n0 + tx * 4 + 0];
    bv.y = bias[n0 + tx * 4 + 1];
    bv.z = bias[n0 + tx * 4 + 2];
    bv.w = bias[n0 + tx * 4 + 3];
#pragma unroll
    for (int mp = 0; mp < 4; mp++) {
        float2 c0 = u2f2(acc[mp][0]);
        float2 c1 = u2f2(acc[mp][1]);
        float2 c2 = u2f2(acc[mp][2]);
        float2 c3 = u2f2(acc[mp][3]);
        size_t mA = (size_t)m0 + ty * 8 + 2 * mp;
        float4 vA, vB;
        vA.x = c0.x + bv.x; vA.y = c1.x + bv.y; vA.z = c2.x + bv.z; vA.w = c3.x + bv.w;
        vB.x = c0.y + bv.x; vB.y = c1.y + bv.y; vB.z = c2.y + bv.z; vB.w = c3.y + bv.w;
        *(float4*)&g_X[((size_t)dir * BB * TT + mA)     * G4 + n0 + tx * 4] = vA;
        *(float4*)&g_X[((size_t)dir * BB * TT + mA + 1) * G4 + n0 + tx * 4] = vB;
    }
}

// =====================================================================
// Kernel 2: PERSISTENT bidirectional LSTM with GROUP-LOCAL flag sync.
// 128 CTAs: (dir:2) x (ks:8) x (bt:8). Group = (dir,bt) = 8 CTAs that
// share a batch tile; each step: publish h(t) (STG), fence+flag by tid0,
// lanes 0-7 poll the 8 group flags, reload h(t) from L2, continue.
// =====================================================================
#define WS_STRIDE 264
#define HS_STRIDE 260
#define SMEM_LSTM ((4 * 32 * WS_STRIDE + 8 * HS_STRIDE) * 4)

__device__ __forceinline__ float sigf(float x) { return 1.f / (1.f + expf(-x)); }

__global__ void lstm_persistent_kernel(const float* __restrict__ Wf_hh,
                                       const float* __restrict__ Wb_hh)
{
    extern __shared__ float sm[];
    float* Ws  = sm;                       // [4*32][WS_STRIDE]
    float* hsm = sm + 4 * 32 * WS_STRIDE;  // [8][HS_STRIDE]

    const int bx  = blockIdx.x;
    const int dir = bx & 1;
    const int ks  = (bx >> 1) & 7;
    const int bt  = bx >> 4;
    const int k0  = ks * 32;
    const int b0  = bt * 8;
    const int tid = threadIdx.x;
    const int grp = bt * 2 + dir;          // 0..15
    const float* __restrict__ W = dir ? Wb_hh : Wf_hh;

    volatile int* myflag = (volatile int*)&g_flagsA[(grp * 8 + ks) * 32];
    volatile int* grpflags = (volatile int*)&g_flagsA[(grp * 8) * 32];

    // cooperative load of W slice into smem (once)
    for (int i = tid; i < 128 * 64; i += 256) {
        int r = i >> 6;
        int c = (i & 63) * 4;
        int gate = r >> 5, k_l = r & 31;
        float4 v = *(const float4*)(W + ((size_t)(gate * 256 + k0 + k_l)) * HDIM + c);
        *(float4*)(Ws + (size_t)r * WS_STRIDE + c) = v;
    }
    for (int i = tid; i < 8 * HS_STRIDE; i += 256) hsm[i] = 0.f;

    const int base = *myflag;              // own slot: stable; all slots equal at launch
    __syncthreads();

    const int b_l = tid & 7, k_l = tid >> 3;
    const int b = b0 + b_l, k = k0 + k_l;
    const float* hr = hsm + b_l * HS_STRIDE;
    const float* wi = Ws + (size_t)(0 * 32 + k_l) * WS_STRIDE;
    const float* wf = Ws + (size_t)(1 * 32 + k_l) * WS_STRIDE;
    const float* wg = Ws + (size_t)(2 * 32 + k_l) * WS_STRIDE;
    const float* wo = Ws + (size_t)(3 * 32 + k_l) * WS_STRIDE;
    const float* xbase = g_X + (((size_t)dir * BB + b) * TT) * G4 + k;
    float*       houtb = g_h + (((size_t)dir * BB + b) * TT) * HDIM + k;

    const int lrow = tid >> 5, lc0 = (tid & 31) * 8;
    const float* hsrcb = g_h + (((size_t)dir * BB + b0 + lrow) * TT) * HDIM + lc0;

    float c_st = 0.f;
    float xi = xbase[0], xf = xbase[256], xg = xbase[512], xo = xbase[768];

    for (int t = 0; t < TT; t++) {
        ulonglong2 ai, af, ag, ao;
        ai.x = ai.y = af.x = af.y = 0ull;
        ag.x = ag.y = ao.x = ao.y = 0ull;

#pragma unroll 4
        for (int kk = 0; kk < HDIM; kk += 8) {
            ulonglong2 h0 = *(const ulonglong2*)(hr + kk);
            ulonglong2 h1 = *(const ulonglong2*)(hr + kk + 4);
            ulonglong2 w;
            w = *(const ulonglong2*)(wi + kk);     ai.x = ffma2(h0.x, w.x, ai.x); ai.y = ffma2(h0.y, w.y, ai.y);
            w = *(const ulonglong2*)(wi + kk + 4); ai.x = ffma2(h1.x, w.x, ai.x); ai.y = ffma2(h1.y, w.y, ai.y);
            w = *(const ulonglong2*)(wf + kk);     af.x = ffma2(h0.x, w.x, af.x); af.y = ffma2(h0.y, w.y, af.y);
            w = *(const ulonglong2*)(wf + kk + 4); af.x = ffma2(h1.x, w.x, af.x); af.y = ffma2(h1.y, w.y, af.y);
            w = *(const ulonglong2*)(wg + kk);     ag.x = ffma2(h0.x, w.x, ag.x); ag.y = ffma2(h0.y, w.y, ag.y);
            w = *(const ulonglong2*)(wg + kk + 4); ag.x = ffma2(h1.x, w.x, ag.x); ag.y = ffma2(h1.y, w.y, ag.y);
            w = *(const ulonglong2*)(wo + kk);     ao.x = ffma2(h0.x, w.x, ao.x); ao.y = ffma2(h0.y, w.y, ao.y);
            w = *(const ulonglong2*)(wo + kk + 4); ao.x = ffma2(h1.x, w.x, ao.x); ao.y = ffma2(h1.y, w.y, ao.y);
        }

        float2 s0, s1;
        s0 = u2f2(ai.x); s1 = u2f2(ai.y);
        float gi = xi + s0.x + s0.y + s1.x + s1.y;
        s0 = u2f2(af.x); s1 = u2f2(af.y);
        float gf = xf + s0.x + s0.y + s1.x + s1.y;
        s0 = u2f2(ag.x); s1 = u2f2(ag.y);
        float gg = xg + s0.x + s0.y + s1.x + s1.y;
        s0 = u2f2(ao.x); s1 = u2f2(ao.y);
        float go = xo + s0.x + s0.y + s1.x + s1.y;

        c_st = sigf(gf) * c_st + sigf(gi) * tanhf(gg);
        float hn = sigf(go) * tanhf(c_st);
        houtb[(size_t)t * HDIM] = hn;     // publish h(t)

        if (t + 1 < TT) {
            // prefetch X(t+1): LDGs drain under the sync
            const float* xr = xbase + (size_t)(t + 1) * G4;
            xi = xr[0]; xf = xr[256]; xg = xr[512]; xo = xr[768];

            const int target = base + t + 1;
            __syncthreads();                       // all h STGs issued (happens-before tid0)
            if (tid == 0) {
                __threadfence();                   // cumulative: drain all CTA's h stores
                *myflag = target;
            }
            if (tid < 8) {
                volatile int* f = grpflags + tid * 32;
                while (*f < target) { }
                __threadfence();                   // acquire peers' h
            }
            __syncthreads();

            // reload h(t) for my 8 batches, all 256 k (L2 hit)
            const float* src = hsrcb + (size_t)t * HDIM;
            float4 v0 = *(const float4*)src;
            float4 v1 = *(const float4*)(src + 4);
            *(float4*)(hsm + lrow * HS_STRIDE + lc0)     = v0;
            *(float4*)(hsm + lrow * HS_STRIDE + lc0 + 4) = v1;
            __syncthreads();
        }
    }
}

// =====================================================================
// Kernel 3: emissions (W_out cached in smem)
// =====================================================================
__global__ void emis_kernel(const int* __restrict__ lengths,
                            const float* __restrict__ W_out,
                            const float* __restrict__ b_out)
{
    __shared__ float Wsm[KTAG * 2 * HDIM];
    __shared__ float bsm[KTAG];

    const int tid = threadIdx.x;
    for (int i = tid; i < KTAG * 2 * HDIM; i += 256) Wsm[i] = W_out[i];
    if (tid < KTAG) bsm[tid] = b_out[tid];
    __syncthreads();

    const int warp = tid >> 5;
    const int lane = tid & 31;
    const int r = blockIdx.x * 8 + warp;
    const int b = r >> 9;
    const int t = r & 511;
    const int len = lengths[b];
    const int tr  = (t < len) ? (len - 1 - t) : t;

    const float* hf = g_h + (((size_t)0 * BB + b) * TT + t)  * HDIM;
    const float* hb = g_h + (((size_t)1 * BB + b) * TT + tr) * HDIM;

    float x[16];
#pragma unroll
    for (int i = 0; i < 8; i++) x[i]     = hf[lane + 32 * i];
#pragma unroll
    for (int i = 0; i < 8; i++) x[8 + i] = hb[lane + 32 * i];

    for (int kk = 0; kk < KTAG; kk++) {
        const float* w = Wsm + (size_t)kk * (2 * HDIM);
        float s = 0.f;
#pragma unroll
        for (int i = 0; i < 8; i++) s += x[i]     * w[lane + 32 * i];
#pragma unroll
        for (int i = 0; i < 8; i++) s += x[8 + i] * w[HDIM + lane + 32 * i];
#pragma unroll
        for (int off = 16; off; off >>= 1) s += __shfl_xor_sync(0xffffffffu, s, off);
        if (lane == 0) g_emis[((size_t)b * TT + t) * KTAG + kk] = s + bsm[kk];
    }
}

// =====================================================================
// Kernel 4: Viterbi. Emissions in smem; order-preserving pairwise-tree
// argmax (depth 5, first-max == jnp.argmax); trans rows padded to 21
// for conflict-free LDS.
// =====================================================================
#define VIT_SMEM 53248

// keep-left-on-tie combine: preserves first-max when a precedes b
#define VCOMB(av, ai_, bv, bi_) { if ((bv) > (av)) { (av) = (bv); (ai_) = (bi_); } }

__global__ void viterbi_kernel(const int* __restrict__ lengths,
                               const int* __restrict__ stop_id_p,
                               const float* __restrict__ trans,
                               float* __restrict__ out)
{
    extern __shared__ char vsm[];
    float* emis_s = (float*)vsm;                 // TT*KTAG
    float* trp    = emis_s + TT * KTAG;          // [KTAG][21] padded
    float* delta  = trp + KTAG * 21;             // KTAG
    float* term   = delta + KTAG;                // KTAG
    unsigned char* bp = (unsigned char*)(term + KTAG);

    const int b = blockIdx.x;
    const int lane = threadIdx.x;

    for (int i = lane; i < TT * KTAG; i += 32)
        emis_s[i] = g_emis[(size_t)b * TT * KTAG + i];
    for (int i = lane; i < KTAG * KTAG; i += 32)
        trp[(i / KTAG) * 21 + (i % KTAG)] = trans[i];
    if (lane < KTAG) delta[lane] = 0.f;
    __syncwarp();

    const int len  = lengths[b];
    const int stop = *stop_id_p;

    for (int t = 0; t < TT; t++) {
        float nd = 0.f; int bpv = 0;
        if (lane < KTAG) {
            if (t < len) {
                const float* trl = trp + lane * 21;
                float v[KTAG];
#pragma unroll
                for (int p = 0; p < KTAG; p++) v[p] = delta[p] + trl[p];
                // 20 -> 10
                float w10[10]; int i10[10];
#pragma unroll
                for (int i = 0; i < 10; i++) {
                    w10[i] = v[2 * i]; i10[i] = 2 * i;
                    VCOMB(w10[i], i10[i], v[2 * i + 1], 2 * i + 1);
                }
                // 10 -> 5
                float w5[5]; int i5[5];
#pragma unroll
                for (int i = 0; i < 5; i++) {
                    w5[i] = w10[2 * i]; i5[i] = i10[2 * i];
                    VCOMB(w5[i], i5[i], w10[2 * i + 1], i10[2 * i + 1]);
                }
                // 5 -> 1 (in order)
                float bv0 = w5[0]; int bi0 = i5[0];
                VCOMB(bv0, bi0, w5[1], i5[1]);
                float bv1 = w5[2]; int bi1 = i5[2];
                VCOMB(bv1, bi1, w5[3], i5[3]);
                VCOMB(bv0, bi0, bv1, bi1);
                VCOMB(bv0, bi0, w5[4], i5[4]);

                nd  = bv0 + emis_s[t * KTAG + lane];
                bpv = bi0;
            } else {
                nd  = delta[lane];
                bpv = lane;
            }
        }
        __syncwarp();
        if (lane < KTAG) { delta[lane] = nd; bp[t * KTAG + lane] = (unsigned char)bpv; }
        __syncwarp();
    }

    if (lane < KTAG) term[lane] = delta[lane] + trp[stop * 21 + lane];
    __syncwarp();

    if (lane == 0) {
        float best = -3.4e38f; int arg = 0;
        for (int j = 0; j < KTAG; j++)
            if (term[j] > best) { best = term[j]; arg = j; }
        out[b] = best;
        float* po = out + BB + (size_t)b * (TT + 1);
        po[TT] = (float)arg;
        int tag = arg;
        for (int t = TT - 1; t >= 0; t--) {
            tag = bp[t * KTAG + tag];
            po[t] = (float)tag;
        }
    }
}

// =====================================================================
// launch
// =====================================================================
extern "C" void kernel_launch(void* const* d_in, const int* in_sizes, int n_in,
                              void* d_out, int out_size)
{
    (void)in_sizes; (void)n_in; (void)out_size;
    const int*   sentence = (const int*)d_in[0];
    const int*   lengths  = (const int*)d_in[1];
    const int*   stop_id  = (const int*)d_in[3];
    const float* emb      = (const float*)d_in[4];
    const float* Wf_ih    = (const float*)d_in[5];
    const float* Wf_hh    = (const float*)d_in[6];
    const float* bf       = (const float*)d_in[7];
    const float* Wb_ih    = (const float*)d_in[8];
    const float* Wb_hh    = (const float*)d_in[9];
    const float* bb       = (const float*)d_in[10];
    const float* W_out    = (const float*)d_in[11];
    const float* b_out    = (const float*)d_in[12];
    const float* trans    = (const float*)d_in[13];
    float* out = (float*)d_out;

    static int attr_set = 0;
    if (!attr_set) {
        cudaFuncSetAttribute(lstm_persistent_kernel,
                             cudaFuncAttributeMaxDynamicSharedMemorySize, SMEM_LSTM);
        cudaFuncSetAttribute(viterbi_kernel,
                             cudaFuncAttributeMaxDynamicSharedMemorySize, VIT_SMEM);
        attr_set = 1;
    }

    dim3 g1(BB * TT / BM, G4 / BN, 2);
    gates_gemm_kernel<<<g1, 256>>>(sentence, lengths, emb, Wf_ih, bf, Wb_ih, bb);

    lstm_persistent_kernel<<<GRID_P, 256, SMEM_LSTM>>>(Wf_hh, Wb_hh);

    emis_kernel<<<BB * TT / 8, 256>>>(lengths, W_out, b_out);

    viterbi_kernel<<<BB, 32, VIT_SMEM>>>(lengths, stop_id, trans, out);
}

// round 6
// speedup vs baseline: 1.3720x; 1.0375x over previous
#include <cuda_runtime.h>
#include <math.h>

// Problem constants
#define BB   64
#define TT   512
#define EE   300
#define HDIM 256
#define G4   1024    // 4*HDIM
#define KTAG 20
#define GRID_P 128

typedef unsigned long long ull;

// ---------------- scratch (device globals; no runtime allocation) ----------------
// g_X blocked: [dir][bt][ks][t][b_l][gate][k_l]  (4KB contiguous per CTA-step)
//   offset = ((dir*8+bt)*8+ks)*(TT*1024) + t*1024 + b_l*128 + gate*32 + k_l
__device__ float g_X[(size_t)2 * BB * TT * G4];
// g_h blocked: [dir][bt][t][b_l][k]   (8KB contiguous per group-step)
//   offset = ((dir*8+bt)*TT + t)*8*HDIM + b_l*HDIM + k
__device__ float g_h[(size_t)2 * BB * TT * HDIM];
__device__ float g_emis[(size_t)BB * TT * KTAG];
__device__ int   g_flagsA[16 * 8 * 32];   // per-(group,ks) monotone flags, 128B apart

// ---------------- packed fp32x2 helpers ----------------
__device__ __forceinline__ ull ffma2(ull a, ull b, ull c) {
    ull d;
    asm("fma.rn.f32x2 %0, %1, %2, %3;" : "=l"(d) : "l"(a), "l"(b), "l"(c));
    return d;
}
__device__ __forceinline__ ull f2u2(float x, float y) {
    ull v;
    asm("mov.b64 %0, {%1, %2};" : "=l"(v) : "f"(x), "f"(y));
    return v;
}
__device__ __forceinline__ float2 u2f2(ull v) {
    float2 f;
    asm("mov.b64 {%0, %1}, %2;" : "=f"(f.x), "=f"(f.y) : "l"(v));
    return f;
}

// =====================================================================
// Kernel 1: fused embedding gather + input-gate GEMM (+bias), both dirs
// Epilogue writes the blocked g_X layout.
// =====================================================================
#define BM 128
#define BN 64
#define BK 16

__global__ void gates_gemm_kernel(const int* __restrict__ sentence,
                                  const int* __restrict__ lengths,
                                  const float* __restrict__ emb,
                                  const float* __restrict__ Wf_ih,
                                  const float* __restrict__ bf,
                                  const float* __restrict__ Wb_ih,
                                  const float* __restrict__ bb)
{
    const int dir = blockIdx.z;
    const int m0  = blockIdx.x * BM;
    const int n0  = blockIdx.y * BN;
    const float* __restrict__ W    = dir ? Wb_ih : Wf_ih;
    const float* __restrict__ bias = dir ? bb    : bf;

    __shared__ float As[BK][BM + 4];
    __shared__ float Bs[BK][BN + 4];
    __shared__ int   tok[BM];

    const int tid = threadIdx.x;
    const int b   = m0 / TT;

    if (tid < BM) {
        int t = (m0 + tid) % TT;
        if (dir) {
            int len = lengths[b];
            t = (t < len) ? (len - 1 - t) : t;
        }
        tok[tid] = sentence[b * TT + t];
    }
    __syncthreads();

    ull acc[4][4];
#pragma unroll
    for (int i = 0; i < 4; i++)
#pragma unroll
        for (int j = 0; j < 4; j++) acc[i][j] = 0ull;

    const int tx = tid & 15;
    const int ty = tid >> 4;

    for (int k0 = 0; k0 < 304; k0 += BK) {
        {
            const int ar = tid >> 1;
            const int ac = (tid & 1) * 8;
            const float* erow = emb + (size_t)tok[ar] * EE;
#pragma unroll
            for (int i = 0; i < 8; i++) {
                int k = k0 + ac + i;
                As[ac + i][ar] = (k < EE) ? erow[k] : 0.f;
            }
        }
        {
            const int bn = tid >> 2;
            const int bk = (tid & 3) * 4;
            const float* wrow = W + (size_t)(n0 + bn) * EE;
#pragma unroll
            for (int i = 0; i < 4; i++) {
                int k = k0 + bk + i;
                Bs[bk + i][bn] = (k < EE) ? wrow[k] : 0.f;
            }
        }
        __syncthreads();

#pragma unroll
        for (int kk = 0; kk < BK; kk++) {
            ulonglong2 a0 = *(const ulonglong2*)&As[kk][ty * 8];
            ulonglong2 a1 = *(const ulonglong2*)&As[kk][ty * 8 + 4];
            float4 bv = *(const float4*)&Bs[kk][tx * 4];
            ull b0 = f2u2(bv.x, bv.x);
            ull b1 = f2u2(bv.y, bv.y);
            ull b2 = f2u2(bv.z, bv.z);
            ull b3 = f2u2(bv.w, bv.w);
            acc[0][0] = ffma2(a0.x, b0, acc[0][0]);
            acc[0][1] = ffma2(a0.x, b1, acc[0][1]);
            acc[0][2] = ffma2(a0.x, b2, acc[0][2]);
            acc[0][3] = ffma2(a0.x, b3, acc[0][3]);
            acc[1][0] = ffma2(a0.y, b0, acc[1][0]);
            acc[1][1] = ffma2(a0.y, b1, acc[1][1]);
            acc[1][2] = ffma2(a0.y, b2, acc[1][2]);
            acc[1][3] = ffma2(a0.y, b3, acc[1][3]);
            acc[2][0] = ffma2(a1.x, b0, acc[2][0]);
            acc[2][1] = ffma2(a1.x, b1, acc[2][1]);
            acc[2][2] = ffma2(a1.x, b2, acc[2][2]);
            acc[2][3] = ffma2(a1.x, b3, acc[2][3]);
            acc[3][0] = ffma2(a1.y, b0, acc[3][0]);
            acc[3][1] = ffma2(a1.y, b1, acc[3][1]);
            acc[3][2] = ffma2(a1.y, b2, acc[3][2]);
            acc[3][3] = ffma2(a1.y, b3, acc[3][3]);
        }
        __syncthreads();
    }

    float4 bv;
    bv.x = bias[n0 + tx * 4 + 0];
    bv.y = bias[n0 + tx * 4 + 1];
    bv.z = bias[n0 + tx * 4 + 2];
    bv.w = bias[n0 + tx * 4 + 3];

    // n block: gate/ks/k_l constant across the float4 (BN=64-aligned, k_l 4-aligned)
    const int n    = n0 + tx * 4;
    const int gate = n >> 8;
    const int kq   = n & 255;
    const int ks   = kq >> 5;
    const int k_l  = kq & 31;

#pragma unroll
    for (int mp = 0; mp < 4; mp++) {
        float2 c0 = u2f2(acc[mp][0]);
        float2 c1 = u2f2(acc[mp][1]);
        float2 c2 = u2f2(acc[mp][2]);
        float2 c3 = u2f2(acc[mp][3]);
        int m = m0 + ty * 8 + 2 * mp;
#pragma unroll
        for (int h = 0; h < 2; h++) {
            int mm = m + h;
            int bb_ = mm >> 9;            // batch
            int t   = mm & 511;
            int bt  = bb_ >> 3;
            int b_l = bb_ & 7;
            size_t off = ((size_t)((dir * 8 + bt) * 8 + ks)) * (TT * 1024)
                       + (size_t)t * 1024 + b_l * 128 + gate * 32 + k_l;
            float4 v;
            if (h == 0) { v.x = c0.x + bv.x; v.y = c1.x + bv.y; v.z = c2.x + bv.z; v.w = c3.x + bv.w; }
            else        { v.x = c0.y + bv.x; v.y = c1.y + bv.y; v.z = c2.y + bv.z; v.w = c3.y + bv.w; }
            *(float4*)&g_X[off] = v;
        }
    }
}

// =====================================================================
// Kernel 2: PERSISTENT bidirectional LSTM, group-local flag sync,
// blocked X (4KB/step contiguous) and blocked h (8KB/step contiguous).
// =====================================================================
#define WS_STRIDE 264
#define HS_STRIDE 260
#define SMEM_LSTM ((4 * 32 * WS_STRIDE + 8 * HS_STRIDE) * 4)

__device__ __forceinline__ float sigf(float x) { return 1.f / (1.f + expf(-x)); }

__global__ void lstm_persistent_kernel(const float* __restrict__ Wf_hh,
                                       const float* __restrict__ Wb_hh)
{
    extern __shared__ float sm[];
    float* Ws  = sm;                       // [4*32][WS_STRIDE]
    float* hsm = sm + 4 * 32 * WS_STRIDE;  // [8][HS_STRIDE]

    const int bx  = blockIdx.x;
    const int dir = bx & 1;
    const int ks  = (bx >> 1) & 7;
    const int bt  = bx >> 4;
    const int k0  = ks * 32;
    const int tid = threadIdx.x;
    const int grp = bt * 2 + dir;          // 0..15
    const float* __restrict__ W = dir ? Wb_hh : Wf_hh;

    volatile int* myflag   = (volatile int*)&g_flagsA[(grp * 8 + ks) * 32];
    volatile int* grpflags = (volatile int*)&g_flagsA[(grp * 8) * 32];

    for (int i = tid; i < 128 * 64; i += 256) {
        int r = i >> 6;
        int c = (i & 63) * 4;
        int gate = r >> 5, k_l = r & 31;
        float4 v = *(const float4*)(W + ((size_t)(gate * 256 + k0 + k_l)) * HDIM + c);
        *(float4*)(Ws + (size_t)r * WS_STRIDE + c) = v;
    }
    for (int i = tid; i < 8 * HS_STRIDE; i += 256) hsm[i] = 0.f;

    const int base = *myflag;
    __syncthreads();

    const int b_l = tid & 7, k_l = tid >> 3;
    const int k = k0 + k_l;
    const float* hr = hsm + b_l * HS_STRIDE;
    const float* wi = Ws + (size_t)(0 * 32 + k_l) * WS_STRIDE;
    const float* wf = Ws + (size_t)(1 * 32 + k_l) * WS_STRIDE;
    const float* wg = Ws + (size_t)(2 * 32 + k_l) * WS_STRIDE;
    const float* wo = Ws + (size_t)(3 * 32 + k_l) * WS_STRIDE;

    // blocked X: contiguous 4KB per (CTA, t)
    const float* xblk = g_X + ((size_t)((dir * 8 + bt) * 8 + ks)) * (TT * 1024)
                             + b_l * 128 + k_l;
    // blocked h: [dir][bt][t][b_l][k]
    float* hout = g_h + ((size_t)(dir * 8 + bt)) * (TT * 8 * HDIM)
                      + b_l * HDIM + k;
    const int lrow = tid >> 5, lc0 = (tid & 31) * 8;
    const float* hsrc = g_h + ((size_t)(dir * 8 + bt)) * (TT * 8 * HDIM)
                            + lrow * HDIM + lc0;

    float c_st = 0.f;
    float xi = xblk[0], xf = xblk[32], xg = xblk[64], xo = xblk[96];

    for (int t = 0; t < TT; t++) {
        ulonglong2 ai, af, ag, ao;
        ai.x = ai.y = af.x = af.y = 0ull;
        ag.x = ag.y = ao.x = ao.y = 0ull;

#pragma unroll 4
        for (int kk = 0; kk < HDIM; kk += 8) {
            ulonglong2 h0 = *(const ulonglong2*)(hr + kk);
            ulonglong2 h1 = *(const ulonglong2*)(hr + kk + 4);
            ulonglong2 w;
            w = *(const ulonglong2*)(wi + kk);     ai.x = ffma2(h0.x, w.x, ai.x); ai.y = ffma2(h0.y, w.y, ai.y);
            w = *(const ulonglong2*)(wi + kk + 4); ai.x = ffma2(h1.x, w.x, ai.x); ai.y = ffma2(h1.y, w.y, ai.y);
            w = *(const ulonglong2*)(wf + kk);     af.x = ffma2(h0.x, w.x, af.x); af.y = ffma2(h0.y, w.y, af.y);
            w = *(const ulonglong2*)(wf + kk + 4); af.x = ffma2(h1.x, w.x, af.x); af.y = ffma2(h1.y, w.y, af.y);
            w = *(const ulonglong2*)(wg + kk);     ag.x = ffma2(h0.x, w.x, ag.x); ag.y = ffma2(h0.y, w.y, ag.y);
            w = *(const ulonglong2*)(wg + kk + 4); ag.x = ffma2(h1.x, w.x, ag.x); ag.y = ffma2(h1.y, w.y, ag.y);
            w = *(const ulonglong2*)(wo + kk);     ao.x = ffma2(h0.x, w.x, ao.x); ao.y = ffma2(h0.y, w.y, ao.y);
            w = *(const ulonglong2*)(wo + kk + 4); ao.x = ffma2(h1.x, w.x, ao.x); ao.y = ffma2(h1.y, w.y, ao.y);
        }

        float2 s0, s1;
        s0 = u2f2(ai.x); s1 = u2f2(ai.y);
        float gi = xi + s0.x + s0.y + s1.x + s1.y;
        s0 = u2f2(af.x); s1 = u2f2(af.y);
        float gf = xf + s0.x + s0.y + s1.x + s1.y;
        s0 = u2f2(ag.x); s1 = u2f2(ag.y);
        float gg = xg + s0.x + s0.y + s1.x + s1.y;
        s0 = u2f2(ao.x); s1 = u2f2(ao.y);
        float go = xo + s0.x + s0.y + s1.x + s1.y;

        c_st = sigf(gf) * c_st + sigf(gi) * tanhf(gg);
        float hn = sigf(go) * tanhf(c_st);
        hout[(size_t)t * (8 * HDIM)] = hn;   // publish h(t) into the group's 8KB block

        if (t + 1 < TT) {
            const int target = base + t + 1;
            __syncthreads();                 // all h STGs issued
            if (tid == 0) {
                __threadfence();             // drain CTA's h stores (cumulative)
                *myflag = target;            // earliest possible publish
            }
            // prefetch X(t+1) while flags propagate
            const float* xr = xblk + (size_t)(t + 1) * 1024;
            xi = xr[0]; xf = xr[32]; xg = xr[64]; xo = xr[96];

            if (tid < 8) {
                volatile int* f = grpflags + tid * 32;
                while (*f < target) { }
                __threadfence();             // acquire peers' h
            }
            __syncthreads();

            // reload h(t): contiguous 1KB per warp
            const float* src = hsrc + (size_t)t * (8 * HDIM);
            float4 v0 = *(const float4*)src;
            float4 v1 = *(const float4*)(src + 4);
            *(float4*)(hsm + lrow * HS_STRIDE + lc0)     = v0;
            *(float4*)(hsm + lrow * HS_STRIDE + lc0 + 4) = v1;
            __syncthreads();
        }
    }
}

// =====================================================================
// Kernel 3: emissions (blocked g_h indexing)
// =====================================================================
__global__ void emis_kernel(const int* __restrict__ lengths,
                            const float* __restrict__ W_out,
                            const float* __restrict__ b_out)
{
    __shared__ float Wsm[KTAG * 2 * HDIM];
    __shared__ float bsm[KTAG];

    const int tid = threadIdx.x;
    for (int i = tid; i < KTAG * 2 * HDIM; i += 256) Wsm[i] = W_out[i];
    if (tid < KTAG) bsm[tid] = b_out[tid];
    __syncthreads();

    const int warp = tid >> 5;
    const int lane = tid & 31;
    const int r = blockIdx.x * 8 + warp;
    const int b = r >> 9;
    const int t = r & 511;
    const int len = lengths[b];
    const int tr  = (t < len) ? (len - 1 - t) : t;
    const int bt = b >> 3, b_l = b & 7;

    const float* hf = g_h + ((size_t)(0 * 8 + bt)) * (TT * 8 * HDIM)
                          + (size_t)t  * (8 * HDIM) + b_l * HDIM;
    const float* hb = g_h + ((size_t)(1 * 8 + bt)) * (TT * 8 * HDIM)
                          + (size_t)tr * (8 * HDIM) + b_l * HDIM;

    float x[16];
#pragma unroll
    for (int i = 0; i < 8; i++) x[i]     = hf[lane + 32 * i];
#pragma unroll
    for (int i = 0; i < 8; i++) x[8 + i] = hb[lane + 32 * i];

    for (int kk = 0; kk < KTAG; kk++) {
        const float* w = Wsm + (size_t)kk * (2 * HDIM);
        float s = 0.f;
#pragma unroll
        for (int i = 0; i < 8; i++) s += x[i]     * w[lane + 32 * i];
#pragma unroll
        for (int i = 0; i < 8; i++) s += x[8 + i] * w[HDIM + lane + 32 * i];
#pragma unroll
        for (int off = 16; off; off >>= 1) s += __shfl_xor_sync(0xffffffffu, s, off);
        if (lane == 0) g_emis[((size_t)b * TT + t) * KTAG + kk] = s + bsm[kk];
    }
}

// =====================================================================
// Kernel 4: Viterbi (unchanged from R5 best)
// =====================================================================
#define VIT_SMEM 53248
#define VCOMB(av, ai_, bv, bi_) { if ((bv) > (av)) { (av) = (bv); (ai_) = (bi_); } }

__global__ void viterbi_kernel(const int* __restrict__ lengths,
                               const int* __restrict__ stop_id_p,
                               const float* __restrict__ trans,
                               float* __restrict__ out)
{
    extern __shared__ char vsm[];
    float* emis_s = (float*)vsm;
    float* trp    = emis_s + TT * KTAG;
    float* delta  = trp + KTAG * 21;
    float* term   = delta + KTAG;
    unsigned char* bp = (unsigned char*)(term + KTAG);

    const int b = blockIdx.x;
    const int lane = threadIdx.x;

    for (int i = lane; i < TT * KTAG; i += 32)
        emis_s[i] = g_emis[(size_t)b * TT * KTAG + i];
    for (int i = lane; i < KTAG * KTAG; i += 32)
        trp[(i / KTAG) * 21 + (i % KTAG)] = trans[i];
    if (lane < KTAG) delta[lane] = 0.f;
    __syncwarp();

    const int len  = lengths[b];
    const int stop = *stop_id_p;

    for (int t = 0; t < TT; t++) {
        float nd = 0.f; int bpv = 0;
        if (lane < KTAG) {
            if (t < len) {
                const float* trl = trp + lane * 21;
                float v[KTAG];
#pragma unroll
                for (int p = 0; p < KTAG; p++) v[p] = delta[p] + trl[p];
                float w10[10]; int i10[10];
#pragma unroll
                for (int i = 0; i < 10; i++) {
                    w10[i] = v[2 * i]; i10[i] = 2 * i;
                    VCOMB(w10[i], i10[i], v[2 * i + 1], 2 * i + 1);
                }
                float w5[5]; int i5[5];
#pragma unroll
                for (int i = 0; i < 5; i++) {
                    w5[i] = w10[2 * i]; i5[i] = i10[2 * i];
                    VCOMB(w5[i], i5[i], w10[2 * i + 1], i10[2 * i + 1]);
                }
                float bv0 = w5[0]; int bi0 = i5[0];
                VCOMB(bv0, bi0, w5[1], i5[1]);
                float bv1 = w5[2]; int bi1 = i5[2];
                VCOMB(bv1, bi1, w5[3], i5[3]);
                VCOMB(bv0, bi0, bv1, bi1);
                VCOMB(bv0, bi0, w5[4], i5[4]);

                nd  = bv0 + emis_s[t * KTAG + lane];
                bpv = bi0;
            } else {
                nd  = delta[lane];
                bpv = lane;
            }
        }
        __syncwarp();
        if (lane < KTAG) { delta[lane] = nd; bp[t * KTAG + lane] = (unsigned char)bpv; }
        __syncwarp();
    }

    if (lane < KTAG) term[lane] = delta[lane] + trp[stop * 21 + lane];
    __syncwarp();

    if (lane == 0) {
        float best = -3.4e38f; int arg = 0;
        for (int j = 0; j < KTAG; j++)
            if (term[j] > best) { best = term[j]; arg = j; }
        out[b] = best;
        float* po = out + BB + (size_t)b * (TT + 1);
        po[TT] = (float)arg;
        int tag = arg;
        for (int t = TT - 1; t >= 0; t--) {
            tag = bp[t * KTAG + tag];
            po[t] = (float)tag;
        }
    }
}

// =====================================================================
// launch
// =====================================================================
extern "C" void kernel_launch(void* const* d_in, const int* in_sizes, int n_in,
                              void* d_out, int out_size)
{
    (void)in_sizes; (void)n_in; (void)out_size;
    const int*   sentence = (const int*)d_in[0];
    const int*   lengths  = (const int*)d_in[1];
    const int*   stop_id  = (const int*)d_in[3];
    const float* emb      = (const float*)d_in[4];
    const float* Wf_ih    = (const float*)d_in[5];
    const float* Wf_hh    = (const float*)d_in[6];
    const float* bf       = (const float*)d_in[7];
    const float* Wb_ih    = (const float*)d_in[8];
    const float* Wb_hh    = (const float*)d_in[9];
    const float* bb       = (const float*)d_in[10];
    const float* W_out    = (const float*)d_in[11];
    const float* b_out    = (const float*)d_in[12];
    const float* trans    = (const float*)d_in[13];
    float* out = (float*)d_out;

    static int attr_set = 0;
    if (!attr_set) {
        cudaFuncSetAttribute(lstm_persistent_kernel,
                             cudaFuncAttributeMaxDynamicSharedMemorySize, SMEM_LSTM);
        cudaFuncSetAttribute(viterbi_kernel,
                             cudaFuncAttributeMaxDynamicSharedMemorySize, VIT_SMEM);
        attr_set = 1;
    }

    dim3 g1(BB * TT / BM, G4 / BN, 2);
    gates_gemm_kernel<<<g1, 256>>>(sentence, lengths, emb, Wf_ih, bf, Wb_ih, bb);

    lstm_persistent_kernel<<<GRID_P, 256, SMEM_LSTM>>>(Wf_hh, Wb_hh);

    emis_kernel<<<BB * TT / 8, 256>>>(lengths, W_out, b_out);

    viterbi_kernel<<<BB, 32, VIT_SMEM>>>(lengths, stop_id, trans, out);
}

// round 7
// speedup vs baseline: 1.5847x; 1.1550x over previous
#include <cuda_runtime.h>
#include <math.h>

// Problem constants
#define BB   64
#define TT   512
#define EE   300
#define HDIM 256
#define G4   1024    // 4*HDIM
#define KTAG 20
#define GRID_P 128

typedef unsigned long long ull;

// ---------------- scratch (device globals; no runtime allocation) ----------------
// g_X blocked: [dir][bt][ks][t][b_l][gate][k_l]
__device__ float g_X[(size_t)2 * BB * TT * G4];
// g_h blocked: [dir][bt][t][b_l][k]
__device__ float g_h[(size_t)2 * BB * TT * HDIM];
__device__ float g_emis[(size_t)BB * TT * KTAG];
__device__ int   g_flagsA[16 * 8 * 32];   // per-(group,ks) monotone flags, 128B apart

// ---------------- packed fp32x2 helpers ----------------
__device__ __forceinline__ ull ffma2(ull a, ull b, ull c) {
    ull d;
    asm("fma.rn.f32x2 %0, %1, %2, %3;" : "=l"(d) : "l"(a), "l"(b), "l"(c));
    return d;
}
__device__ __forceinline__ ull f2u2(float x, float y) {
    ull v;
    asm("mov.b64 %0, {%1, %2};" : "=l"(v) : "f"(x), "f"(y));
    return v;
}
__device__ __forceinline__ float2 u2f2(ull v) {
    float2 f;
    asm("mov.b64 {%0, %1}, %2;" : "=f"(f.x), "=f"(f.y) : "l"(v));
    return f;
}

// =====================================================================
// Kernel 1: fused embedding gather + input-gate GEMM (+bias), both dirs
// (unchanged from R6; writes blocked g_X)
// =====================================================================
#define BM 128
#define BN 64
#define BK 16

__global__ void gates_gemm_kernel(const int* __restrict__ sentence,
                                  const int* __restrict__ lengths,
                                  const float* __restrict__ emb,
                                  const float* __restrict__ Wf_ih,
                                  const float* __restrict__ bf,
                                  const float* __restrict__ Wb_ih,
                                  const float* __restrict__ bb)
{
    const int dir = blockIdx.z;
    const int m0  = blockIdx.x * BM;
    const int n0  = blockIdx.y * BN;
    const float* __restrict__ W    = dir ? Wb_ih : Wf_ih;
    const float* __restrict__ bias = dir ? bb    : bf;

    __shared__ float As[BK][BM + 4];
    __shared__ float Bs[BK][BN + 4];
    __shared__ int   tok[BM];

    const int tid = threadIdx.x;
    const int b   = m0 / TT;

    if (tid < BM) {
        int t = (m0 + tid) % TT;
        if (dir) {
            int len = lengths[b];
            t = (t < len) ? (len - 1 - t) : t;
        }
        tok[tid] = sentence[b * TT + t];
    }
    __syncthreads();

    ull acc[4][4];
#pragma unroll
    for (int i = 0; i < 4; i++)
#pragma unroll
        for (int j = 0; j < 4; j++) acc[i][j] = 0ull;

    const int tx = tid & 15;
    const int ty = tid >> 4;

    for (int k0 = 0; k0 < 304; k0 += BK) {
        {
            const int ar = tid >> 1;
            const int ac = (tid & 1) * 8;
            const float* erow = emb + (size_t)tok[ar] * EE;
#pragma unroll
            for (int i = 0; i < 8; i++) {
                int k = k0 + ac + i;
                As[ac + i][ar] = (k < EE) ? erow[k] : 0.f;
            }
        }
        {
            const int bn = tid >> 2;
            const int bk = (tid & 3) * 4;
            const float* wrow = W + (size_t)(n0 + bn) * EE;
#pragma unroll
            for (int i = 0; i < 4; i++) {
                int k = k0 + bk + i;
                Bs[bk + i][bn] = (k < EE) ? wrow[k] : 0.f;
            }
        }
        __syncthreads();

#pragma unroll
        for (int kk = 0; kk < BK; kk++) {
            ulonglong2 a0 = *(const ulonglong2*)&As[kk][ty * 8];
            ulonglong2 a1 = *(const ulonglong2*)&As[kk][ty * 8 + 4];
            float4 bv = *(const float4*)&Bs[kk][tx * 4];
            ull b0 = f2u2(bv.x, bv.x);
            ull b1 = f2u2(bv.y, bv.y);
            ull b2 = f2u2(bv.z, bv.z);
            ull b3 = f2u2(bv.w, bv.w);
            acc[0][0] = ffma2(a0.x, b0, acc[0][0]);
            acc[0][1] = ffma2(a0.x, b1, acc[0][1]);
            acc[0][2] = ffma2(a0.x, b2, acc[0][2]);
            acc[0][3] = ffma2(a0.x, b3, acc[0][3]);
            acc[1][0] = ffma2(a0.y, b0, acc[1][0]);
            acc[1][1] = ffma2(a0.y, b1, acc[1][1]);
            acc[1][2] = ffma2(a0.y, b2, acc[1][2]);
            acc[1][3] = ffma2(a0.y, b3, acc[1][3]);
            acc[2][0] = ffma2(a1.x, b0, acc[2][0]);
            acc[2][1] = ffma2(a1.x, b1, acc[2][1]);
            acc[2][2] = ffma2(a1.x, b2, acc[2][2]);
            acc[2][3] = ffma2(a1.x, b3, acc[2][3]);
            acc[3][0] = ffma2(a1.y, b0, acc[3][0]);
            acc[3][1] = ffma2(a1.y, b1, acc[3][1]);
            acc[3][2] = ffma2(a1.y, b2, acc[3][2]);
            acc[3][3] = ffma2(a1.y, b3, acc[3][3]);
        }
        __syncthreads();
    }

    float4 bv;
    bv.x = bias[n0 + tx * 4 + 0];
    bv.y = bias[n0 + tx * 4 + 1];
    bv.z = bias[n0 + tx * 4 + 2];
    bv.w = bias[n0 + tx * 4 + 3];

    const int n    = n0 + tx * 4;
    const int gate = n >> 8;
    const int kq   = n & 255;
    const int ks   = kq >> 5;
    const int k_l  = kq & 31;

#pragma unroll
    for (int mp = 0; mp < 4; mp++) {
        float2 c0 = u2f2(acc[mp][0]);
        float2 c1 = u2f2(acc[mp][1]);
        float2 c2 = u2f2(acc[mp][2]);
        float2 c3 = u2f2(acc[mp][3]);
        int m = m0 + ty * 8 + 2 * mp;
#pragma unroll
        for (int h = 0; h < 2; h++) {
            int mm = m + h;
            int bb_ = mm >> 9;
            int t   = mm & 511;
            int bt  = bb_ >> 3;
            int b_l = bb_ & 7;
            size_t off = ((size_t)((dir * 8 + bt) * 8 + ks)) * (TT * 1024)
                       + (size_t)t * 1024 + b_l * 128 + gate * 32 + k_l;
            float4 v;
            if (h == 0) { v.x = c0.x + bv.x; v.y = c1.x + bv.y; v.z = c2.x + bv.z; v.w = c3.x + bv.w; }
            else        { v.x = c0.y + bv.x; v.y = c1.y + bv.y; v.z = c2.y + bv.z; v.w = c3.y + bv.w; }
            *(float4*)&g_X[off] = v;
        }
    }
}

// =====================================================================
// Kernel 2: PERSISTENT LSTM, crossbar-lean.
// Warp w = kk-slice [32w,32w+32) partial sums for all 32 k x 8 b.
//   W: Wp[g][kk2][k] f32x2-packed, pad 33 -> lane-coalesced LDS.64, each
//      byte crosses the crossbar once per SM per step.
//   h: hsm[b][kk] -> warp-uniform LDS.64 (broadcast).
// Partials via psum smem; final pass thread (b=tid>>5, k=tid&31).
// Group-local flag sync as R6.
// =====================================================================
#define WP_ULL (4 * 128 * 33)                    // 16896 ull
#define SMEM_LSTM (WP_ULL * 8 + 2048 * 4 + 8192 * 4)   // 135168+8192+32768 = 176128

__device__ __forceinline__ float sigf(float x) { return 1.f / (1.f + expf(-x)); }

__global__ void __launch_bounds__(256, 1)
lstm_persistent_kernel(const float* __restrict__ Wf_hh,
                       const float* __restrict__ Wb_hh)
{
    extern __shared__ char smraw[];
    ull*   Wp   = (ull*)smraw;                   // [4][128][33] ull
    float* hsm  = (float*)(Wp + WP_ULL);         // [8][256]
    float* ps   = hsm + 2048;                    // [8][4][8][32]
    ull*   hsmu = (ull*)hsm;                     // [8][128] ull view

    const int bx  = blockIdx.x;
    const int dir = bx & 1;
    const int ks  = (bx >> 1) & 7;
    const int bt  = bx >> 4;
    const int k0  = ks * 32;
    const int tid = threadIdx.x;
    const int grp = bt * 2 + dir;
    const float* __restrict__ W = dir ? Wb_hh : Wf_hh;

    volatile int* myflag   = (volatile int*)&g_flagsA[(grp * 8 + ks) * 32];
    volatile int* grpflags = (volatile int*)&g_flagsA[(grp * 8) * 32];

    // one-time: pack W slice transposed: Wp[(g*128+j)*33+kl] = (W[g*256+k0+kl][2j], [2j+1])
    for (int i = tid; i < 128 * 128; i += 256) {
        int r = i >> 7;               // g*32 + kl
        int j = i & 127;              // kk pair index
        int g = r >> 5, kl = r & 31;
        ull v = *(const ull*)(W + (size_t)(g * 256 + k0 + kl) * HDIM + 2 * j);
        Wp[(g * 128 + j) * 33 + kl] = v;
    }
    for (int i = tid; i < 2048; i += 256) hsm[i] = 0.f;

    const int base = *myflag;
    __syncthreads();

    const int lane = tid & 31;
    const int warp = tid >> 5;
    const int b2   = warp;            // final-pass batch

    // X for final pass: blocked [t][b_l][gate][k_l]
    const float* xme = g_X + ((size_t)((dir * 8 + bt) * 8 + ks)) * (TT * 1024)
                           + b2 * 128 + lane;
    // h publish (blocked [t][b_l][k], k global)
    float* hme = g_h + ((size_t)(dir * 8 + bt)) * (TT * 8 * HDIM)
                     + b2 * HDIM + (k0 + lane);
    // hsm reload source: thread loads 8 floats of (b=warp, kk=lane*8..)
    const float* hsrc = g_h + ((size_t)(dir * 8 + bt)) * (TT * 8 * HDIM)
                            + warp * HDIM + lane * 8;

    const int kkb = warp * 16;        // this warp's kk-pair base

    float c_st = 0.f;

    for (int t = 0; t < TT; t++) {
        // prefetch X(t) for final pass (hidden under inner loop)
        const float* xr = xme + (size_t)t * 1024;
        float xi = xr[0], xf = xr[32], xg = xr[64], xo = xr[96];

        // ---- partial dot products over this warp's kk slice ----
        ull acc[4][8];
#pragma unroll
        for (int g = 0; g < 4; g++)
#pragma unroll
            for (int b = 0; b < 8; b++) acc[g][b] = 0ull;

#pragma unroll 4
        for (int c = 0; c < 16; c++) {
            int kk2 = kkb + c;
            ull w0 = Wp[(0 * 128 + kk2) * 33 + lane];
            ull w1 = Wp[(1 * 128 + kk2) * 33 + lane];
            ull w2 = Wp[(2 * 128 + kk2) * 33 + lane];
            ull w3 = Wp[(3 * 128 + kk2) * 33 + lane];
#pragma unroll
            for (int b = 0; b < 8; b++) {
                ull h2 = hsmu[b * 128 + kk2];     // warp-uniform broadcast
                acc[0][b] = ffma2(h2, w0, acc[0][b]);
                acc[1][b] = ffma2(h2, w1, acc[1][b]);
                acc[2][b] = ffma2(h2, w2, acc[2][b]);
                acc[3][b] = ffma2(h2, w3, acc[3][b]);
            }
        }

        // ---- write partials ----
#pragma unroll
        for (int g = 0; g < 4; g++)
#pragma unroll
            for (int b = 0; b < 8; b++) {
                float2 s = u2f2(acc[g][b]);
                ps[((warp * 4 + g) * 8 + b) * 32 + lane] = s.x + s.y;
            }
        __syncthreads();

        // ---- reduce 8 warps + pointwise for (b2, k0+lane) ----
        float s0 = 0.f, s1 = 0.f, s2 = 0.f, s3 = 0.f;
#pragma unroll
        for (int w = 0; w < 8; w++) {
            s0 += ps[((w * 4 + 0) * 8 + b2) * 32 + lane];
            s1 += ps[((w * 4 + 1) * 8 + b2) * 32 + lane];
            s2 += ps[((w * 4 + 2) * 8 + b2) * 32 + lane];
            s3 += ps[((w * 4 + 3) * 8 + b2) * 32 + lane];
        }
        float gi = xi + s0;
        float gf = xf + s1;
        float gg = xg + s2;
        float go = xo + s3;

        c_st = sigf(gf) * c_st + sigf(gi) * tanhf(gg);
        float hn = sigf(go) * tanhf(c_st);
        hme[(size_t)t * (8 * HDIM)] = hn;         // publish h(t)

        if (t + 1 < TT) {
            const int target = base + t + 1;
            __syncthreads();                      // h STGs issued; psum reads done
            if (tid == 0) {
                __threadfence();                  // drain this CTA's h stores
                *myflag = target;
            }
            if (tid < 8) {
                volatile int* f = grpflags + tid * 32;
                while (*f < target) { }
                __threadfence();                  // acquire peers' h
            }
            __syncthreads();

            // reload h(t): hsm[b=warp][lane*8 .. +8]
            const float* src = hsrc + (size_t)t * (8 * HDIM);
            float4 v0 = *(const float4*)src;
            float4 v1 = *(const float4*)(src + 4);
            *(float4*)&hsm[warp * 256 + lane * 8]     = v0;
            *(float4*)&hsm[warp * 256 + lane * 8 + 4] = v1;
            __syncthreads();
        }
    }
}

// =====================================================================
// Kernel 3: emissions (blocked g_h indexing; unchanged)
// =====================================================================
__global__ void emis_kernel(const int* __restrict__ lengths,
                            const float* __restrict__ W_out,
                            const float* __restrict__ b_out)
{
    __shared__ float Wsm[KTAG * 2 * HDIM];
    __shared__ float bsm[KTAG];

    const int tid = threadIdx.x;
    for (int i = tid; i < KTAG * 2 * HDIM; i += 256) Wsm[i] = W_out[i];
    if (tid < KTAG) bsm[tid] = b_out[tid];
    __syncthreads();

    const int warp = tid >> 5;
    const int lane = tid & 31;
    const int r = blockIdx.x * 8 + warp;
    const int b = r >> 9;
    const int t = r & 511;
    const int len = lengths[b];
    const int tr  = (t < len) ? (len - 1 - t) : t;
    const int bt = b >> 3, b_l = b & 7;

    const float* hf = g_h + ((size_t)(0 * 8 + bt)) * (TT * 8 * HDIM)
                          + (size_t)t  * (8 * HDIM) + b_l * HDIM;
    const float* hb = g_h + ((size_t)(1 * 8 + bt)) * (TT * 8 * HDIM)
                          + (size_t)tr * (8 * HDIM) + b_l * HDIM;

    float x[16];
#pragma unroll
    for (int i = 0; i < 8; i++) x[i]     = hf[lane + 32 * i];
#pragma unroll
    for (int i = 0; i < 8; i++) x[8 + i] = hb[lane + 32 * i];

    for (int kk = 0; kk < KTAG; kk++) {
        const float* w = Wsm + (size_t)kk * (2 * HDIM);
        float s = 0.f;
#pragma unroll
        for (int i = 0; i < 8; i++) s += x[i]     * w[lane + 32 * i];
#pragma unroll
        for (int i = 0; i < 8; i++) s += x[8 + i] * w[HDIM + lane + 32 * i];
#pragma unroll
        for (int off = 16; off; off >>= 1) s += __shfl_xor_sync(0xffffffffu, s, off);
        if (lane == 0) g_emis[((size_t)b * TT + t) * KTAG + kk] = s + bsm[kk];
    }
}

// =====================================================================
// Kernel 4: Viterbi (unchanged from R6)
// =====================================================================
#define VIT_SMEM 53248
#define VCOMB(av, ai_, bv, bi_) { if ((bv) > (av)) { (av) = (bv); (ai_) = (bi_); } }

__global__ void viterbi_kernel(const int* __restrict__ lengths,
                               const int* __restrict__ stop_id_p,
                               const float* __restrict__ trans,
                               float* __restrict__ out)
{
    extern __shared__ char vsm[];
    float* emis_s = (float*)vsm;
    float* trp    = emis_s + TT * KTAG;
    float* delta  = trp + KTAG * 21;
    float* term   = delta + KTAG;
    unsigned char* bp = (unsigned char*)(term + KTAG);

    const int b = blockIdx.x;
    const int lane = threadIdx.x;

    for (int i = lane; i < TT * KTAG; i += 32)
        emis_s[i] = g_emis[(size_t)b * TT * KTAG + i];
    for (int i = lane; i < KTAG * KTAG; i += 32)
        trp[(i / KTAG) * 21 + (i % KTAG)] = trans[i];
    if (lane < KTAG) delta[lane] = 0.f;
    __syncwarp();

    const int len  = lengths[b];
    const int stop = *stop_id_p;

    for (int t = 0; t < TT; t++) {
        float nd = 0.f; int bpv = 0;
        if (lane < KTAG) {
            if (t < len) {
                const float* trl = trp + lane * 21;
                float v[KTAG];
#pragma unroll
                for (int p = 0; p < KTAG; p++) v[p] = delta[p] + trl[p];
                float w10[10]; int i10[10];
#pragma unroll
                for (int i = 0; i < 10; i++) {
                    w10[i] = v[2 * i]; i10[i] = 2 * i;
                    VCOMB(w10[i], i10[i], v[2 * i + 1], 2 * i + 1);
                }
                float w5[5]; int i5[5];
#pragma unroll
                for (int i = 0; i < 5; i++) {
                    w5[i] = w10[2 * i]; i5[i] = i10[2 * i];
                    VCOMB(w5[i], i5[i], w10[2 * i + 1], i10[2 * i + 1]);
                }
                float bv0 = w5[0]; int bi0 = i5[0];
                VCOMB(bv0, bi0, w5[1], i5[1]);
                float bv1 = w5[2]; int bi1 = i5[2];
                VCOMB(bv1, bi1, w5[3], i5[3]);
                VCOMB(bv0, bi0, bv1, bi1);
                VCOMB(bv0, bi0, w5[4], i5[4]);

                nd  = bv0 + emis_s[t * KTAG + lane];
                bpv = bi0;
            } else {
                nd  = delta[lane];
                bpv = lane;
            }
        }
        __syncwarp();
        if (lane < KTAG) { delta[lane] = nd; bp[t * KTAG + lane] = (unsigned char)bpv; }
        __syncwarp();
    }

    if (lane < KTAG) term[lane] = delta[lane] + trp[stop * 21 + lane];
    __syncwarp();

    if (lane == 0) {
        float best = -3.4e38f; int arg = 0;
        for (int j = 0; j < KTAG; j++)
            if (term[j] > best) { best = term[j]; arg = j; }
        out[b] = best;
        float* po = out + BB + (size_t)b * (TT + 1);
        po[TT] = (float)arg;
        int tag = arg;
        for (int t = TT - 1; t >= 0; t--) {
            tag = bp[t * KTAG + tag];
            po[t] = (float)tag;
        }
    }
}

// =====================================================================
// launch
// =====================================================================
extern "C" void kernel_launch(void* const* d_in, const int* in_sizes, int n_in,
                              void* d_out, int out_size)
{
    (void)in_sizes; (void)n_in; (void)out_size;
    const int*   sentence = (const int*)d_in[0];
    const int*   lengths  = (const int*)d_in[1];
    const int*   stop_id  = (const int*)d_in[3];
    const float* emb      = (const float*)d_in[4];
    const float* Wf_ih    = (const float*)d_in[5];
    const float* Wf_hh    = (const float*)d_in[6];
    const float* bf       = (const float*)d_in[7];
    const float* Wb_ih    = (const float*)d_in[8];
    const float* Wb_hh    = (const float*)d_in[9];
    const float* bb       = (const float*)d_in[10];
    const float* W_out    = (const float*)d_in[11];
    const float* b_out    = (const float*)d_in[12];
    const float* trans    = (const float*)d_in[13];
    float* out = (float*)d_out;

    static int attr_set = 0;
    if (!attr_set) {
        cudaFuncSetAttribute(lstm_persistent_kernel,
                             cudaFuncAttributeMaxDynamicSharedMemorySize, SMEM_LSTM);
        cudaFuncSetAttribute(viterbi_kernel,
                             cudaFuncAttributeMaxDynamicSharedMemorySize, VIT_SMEM);
        attr_set = 1;
    }

    dim3 g1(BB * TT / BM, G4 / BN, 2);
    gates_gemm_kernel<<<g1, 256>>>(sentence, lengths, emb, Wf_ih, bf, Wb_ih, bb);

    lstm_persistent_kernel<<<GRID_P, 256, SMEM_LSTM>>>(Wf_hh, Wb_hh);

    emis_kernel<<<BB * TT / 8, 256>>>(lengths, W_out, b_out);

    viterbi_kernel<<<BB, 32, VIT_SMEM>>>(lengths, stop_id, trans, out);
}

// round 8
// speedup vs baseline: 1.6946x; 1.0693x over previous
#include <cuda_runtime.h>
#include <math.h>

// Problem constants
#define BB   64
#define TT   512
#define EE   300
#define HDIM 256
#define G4   1024    // 4*HDIM
#define KTAG 20
#define GRID_P 128

typedef unsigned long long ull;

// ---------------- scratch (device globals; no runtime allocation) ----------------
// g_X blocked: [dir][bt][ks][t][b_l][gate][k_l]
__device__ float g_X[(size_t)2 * BB * TT * G4];
// g_h blocked: [dir][bt][t][b_l][k]
__device__ float g_h[(size_t)2 * BB * TT * HDIM];
__device__ float g_emis[(size_t)BB * TT * KTAG];
__device__ int   g_flagsA[16 * 8 * 32];   // per-(group,ks) monotone flags, 128B apart

// ---------------- packed fp32x2 helpers ----------------
__device__ __forceinline__ ull ffma2(ull a, ull b, ull c) {
    ull d;
    asm("fma.rn.f32x2 %0, %1, %2, %3;" : "=l"(d) : "l"(a), "l"(b), "l"(c));
    return d;
}
__device__ __forceinline__ ull f2u2(float x, float y) {
    ull v;
    asm("mov.b64 %0, {%1, %2};" : "=l"(v) : "f"(x), "f"(y));
    return v;
}
__device__ __forceinline__ float2 u2f2(ull v) {
    float2 f;
    asm("mov.b64 {%0, %1}, %2;" : "=f"(f.x), "=f"(f.y) : "l"(v));
    return f;
}

// =====================================================================
// Kernel 1: fused embedding gather + input-gate GEMM (+bias), both dirs
// (unchanged; writes blocked g_X)
// =====================================================================
#define BM 128
#define BN 64
#define BK 16

__global__ void gates_gemm_kernel(const int* __restrict__ sentence,
                                  const int* __restrict__ lengths,
                                  const float* __restrict__ emb,
                                  const float* __restrict__ Wf_ih,
                                  const float* __restrict__ bf,
                                  const float* __restrict__ Wb_ih,
                                  const float* __restrict__ bb)
{
    const int dir = blockIdx.z;
    const int m0  = blockIdx.x * BM;
    const int n0  = blockIdx.y * BN;
    const float* __restrict__ W    = dir ? Wb_ih : Wf_ih;
    const float* __restrict__ bias = dir ? bb    : bf;

    __shared__ float As[BK][BM + 4];
    __shared__ float Bs[BK][BN + 4];
    __shared__ int   tok[BM];

    const int tid = threadIdx.x;
    const int b   = m0 / TT;

    if (tid < BM) {
        int t = (m0 + tid) % TT;
        if (dir) {
            int len = lengths[b];
            t = (t < len) ? (len - 1 - t) : t;
        }
        tok[tid] = sentence[b * TT + t];
    }
    __syncthreads();

    ull acc[4][4];
#pragma unroll
    for (int i = 0; i < 4; i++)
#pragma unroll
        for (int j = 0; j < 4; j++) acc[i][j] = 0ull;

    const int tx = tid & 15;
    const int ty = tid >> 4;

    for (int k0 = 0; k0 < 304; k0 += BK) {
        {
            const int ar = tid >> 1;
            const int ac = (tid & 1) * 8;
            const float* erow = emb + (size_t)tok[ar] * EE;
#pragma unroll
            for (int i = 0; i < 8; i++) {
                int k = k0 + ac + i;
                As[ac + i][ar] = (k < EE) ? erow[k] : 0.f;
            }
        }
        {
            const int bn = tid >> 2;
            const int bk = (tid & 3) * 4;
            const float* wrow = W + (size_t)(n0 + bn) * EE;
#pragma unroll
            for (int i = 0; i < 4; i++) {
                int k = k0 + bk + i;
                Bs[bk + i][bn] = (k < EE) ? wrow[k] : 0.f;
            }
        }
        __syncthreads();

#pragma unroll
        for (int kk = 0; kk < BK; kk++) {
            ulonglong2 a0 = *(const ulonglong2*)&As[kk][ty * 8];
            ulonglong2 a1 = *(const ulonglong2*)&As[kk][ty * 8 + 4];
            float4 bv = *(const float4*)&Bs[kk][tx * 4];
            ull b0 = f2u2(bv.x, bv.x);
            ull b1 = f2u2(bv.y, bv.y);
            ull b2 = f2u2(bv.z, bv.z);
            ull b3 = f2u2(bv.w, bv.w);
            acc[0][0] = ffma2(a0.x, b0, acc[0][0]);
            acc[0][1] = ffma2(a0.x, b1, acc[0][1]);
            acc[0][2] = ffma2(a0.x, b2, acc[0][2]);
            acc[0][3] = ffma2(a0.x, b3, acc[0][3]);
            acc[1][0] = ffma2(a0.y, b0, acc[1][0]);
            acc[1][1] = ffma2(a0.y, b1, acc[1][1]);
            acc[1][2] = ffma2(a0.y, b2, acc[1][2]);
            acc[1][3] = ffma2(a0.y, b3, acc[1][3]);
            acc[2][0] = ffma2(a1.x, b0, acc[2][0]);
            acc[2][1] = ffma2(a1.x, b1, acc[2][1]);
            acc[2][2] = ffma2(a1.x, b2, acc[2][2]);
            acc[2][3] = ffma2(a1.x, b3, acc[2][3]);
            acc[3][0] = ffma2(a1.y, b0, acc[3][0]);
            acc[3][1] = ffma2(a1.y, b1, acc[3][1]);
            acc[3][2] = ffma2(a1.y, b2, acc[3][2]);
            acc[3][3] = ffma2(a1.y, b3, acc[3][3]);
        }
        __syncthreads();
    }

    float4 bv;
    bv.x = bias[n0 + tx * 4 + 0];
    bv.y = bias[n0 + tx * 4 + 1];
    bv.z = bias[n0 + tx * 4 + 2];
    bv.w = bias[n0 + tx * 4 + 3];

    const int n    = n0 + tx * 4;
    const int gate = n >> 8;
    const int kq   = n & 255;
    const int ks   = kq >> 5;
    const int k_l  = kq & 31;

#pragma unroll
    for (int mp = 0; mp < 4; mp++) {
        float2 c0 = u2f2(acc[mp][0]);
        float2 c1 = u2f2(acc[mp][1]);
        float2 c2 = u2f2(acc[mp][2]);
        float2 c3 = u2f2(acc[mp][3]);
        int m = m0 + ty * 8 + 2 * mp;
#pragma unroll
        for (int h = 0; h < 2; h++) {
            int mm = m + h;
            int bb_ = mm >> 9;
            int t   = mm & 511;
            int bt  = bb_ >> 3;
            int b_l = bb_ & 7;
            size_t off = ((size_t)((dir * 8 + bt) * 8 + ks)) * (TT * 1024)
                       + (size_t)t * 1024 + b_l * 128 + gate * 32 + k_l;
            float4 v;
            if (h == 0) { v.x = c0.x + bv.x; v.y = c1.x + bv.y; v.z = c2.x + bv.z; v.w = c3.x + bv.w; }
            else        { v.x = c0.y + bv.x; v.y = c1.y + bv.y; v.z = c2.y + bv.z; v.w = c3.y + bv.w; }
            *(float4*)&g_X[off] = v;
        }
    }
}

// =====================================================================
// Kernel 2: PERSISTENT LSTM, crossbar-lean + slim sync.
//  - release/acquire flags (no MEMBAR), per-thread dependency-exact poll
//  - 3 __syncthreads per step
// =====================================================================
#define WP_ULL (4 * 128 * 33)
#define SMEM_LSTM (WP_ULL * 8 + 2048 * 4 + 8192 * 4)

__device__ __forceinline__ float sigf(float x) { return 1.f / (1.f + expf(-x)); }

__global__ void __launch_bounds__(256, 1)
lstm_persistent_kernel(const float* __restrict__ Wf_hh,
                       const float* __restrict__ Wb_hh)
{
    extern __shared__ char smraw[];
    ull*   Wp   = (ull*)smraw;                   // [4][128][33] ull
    float* hsm  = (float*)(Wp + WP_ULL);         // [8][256]
    float* ps   = hsm + 2048;                    // [8][4][8][32]
    ull*   hsmu = (ull*)hsm;                     // [8][128] ull view

    const int bx  = blockIdx.x;
    const int dir = bx & 1;
    const int ks  = (bx >> 1) & 7;
    const int bt  = bx >> 4;
    const int k0  = ks * 32;
    const int tid = threadIdx.x;
    const int grp = bt * 2 + dir;
    const float* __restrict__ W = dir ? Wb_hh : Wf_hh;

    int* myflag = &g_flagsA[(grp * 8 + ks) * 32];

    for (int i = tid; i < 128 * 128; i += 256) {
        int r = i >> 7;
        int j = i & 127;
        int g = r >> 5, kl = r & 31;
        ull v = *(const ull*)(W + (size_t)(g * 256 + k0 + kl) * HDIM + 2 * j);
        Wp[(g * 128 + j) * 33 + kl] = v;
    }
    for (int i = tid; i < 2048; i += 256) hsm[i] = 0.f;

    const int base = *(volatile int*)myflag;
    __syncthreads();

    const int lane = tid & 31;
    const int warp = tid >> 5;
    const int b2   = warp;

    // per-thread producer flag: reload k-range [lane*8, lane*8+8) lives in slice lane>>2
    int* depflag = &g_flagsA[(grp * 8 + (lane >> 2)) * 32];

    const float* xme = g_X + ((size_t)((dir * 8 + bt) * 8 + ks)) * (TT * 1024)
                           + b2 * 128 + lane;
    float* hme = g_h + ((size_t)(dir * 8 + bt)) * (TT * 8 * HDIM)
                     + b2 * HDIM + (k0 + lane);
    const float* hsrc = g_h + ((size_t)(dir * 8 + bt)) * (TT * 8 * HDIM)
                            + warp * HDIM + lane * 8;

    const int kkb = warp * 16;

    float c_st = 0.f;

    for (int t = 0; t < TT; t++) {
        const float* xr = xme + (size_t)t * 1024;
        float xi = xr[0], xf = xr[32], xg = xr[64], xo = xr[96];

        // ---- partial dot products over this warp's kk slice ----
        ull acc[4][8];
#pragma unroll
        for (int g = 0; g < 4; g++)
#pragma unroll
            for (int b = 0; b < 8; b++) acc[g][b] = 0ull;

#pragma unroll 4
        for (int c = 0; c < 16; c++) {
            int kk2 = kkb + c;
            ull w0 = Wp[(0 * 128 + kk2) * 33 + lane];
            ull w1 = Wp[(1 * 128 + kk2) * 33 + lane];
            ull w2 = Wp[(2 * 128 + kk2) * 33 + lane];
            ull w3 = Wp[(3 * 128 + kk2) * 33 + lane];
#pragma unroll
            for (int b = 0; b < 8; b++) {
                ull h2 = hsmu[b * 128 + kk2];
                acc[0][b] = ffma2(h2, w0, acc[0][b]);
                acc[1][b] = ffma2(h2, w1, acc[1][b]);
                acc[2][b] = ffma2(h2, w2, acc[2][b]);
                acc[3][b] = ffma2(h2, w3, acc[3][b]);
            }
        }

#pragma unroll
        for (int g = 0; g < 4; g++)
#pragma unroll
            for (int b = 0; b < 8; b++) {
                float2 s = u2f2(acc[g][b]);
                ps[((warp * 4 + g) * 8 + b) * 32 + lane] = s.x + s.y;
            }
        __syncthreads();                          // psum visible

        float s0 = 0.f, s1 = 0.f, s2 = 0.f, s3 = 0.f;
#pragma unroll
        for (int w = 0; w < 8; w++) {
            s0 += ps[((w * 4 + 0) * 8 + b2) * 32 + lane];
            s1 += ps[((w * 4 + 1) * 8 + b2) * 32 + lane];
            s2 += ps[((w * 4 + 2) * 8 + b2) * 32 + lane];
            s3 += ps[((w * 4 + 3) * 8 + b2) * 32 + lane];
        }
        float gi = xi + s0;
        float gf = xf + s1;
        float gg = xg + s2;
        float go = xo + s3;

        c_st = sigf(gf) * c_st + sigf(gi) * tanhf(gg);
        float hn = sigf(go) * tanhf(c_st);
        hme[(size_t)t * (8 * HDIM)] = hn;         // publish h(t)

        if (t + 1 < TT) {
            const int target = base + t + 1;
            __syncthreads();                      // all h STGs + psum reads done
            if (tid == 0) {
                asm volatile("st.release.gpu.global.b32 [%0], %1;"
                             :: "l"(myflag), "r"(target) : "memory");
            }

            // prefetch X(t+1) while flags propagate
            const float* xn = xme + (size_t)(t + 1) * 1024;
            xi = xn[0]; xf = xn[32]; xg = xn[64]; xo = xn[96];
            (void)xi; (void)xf; (void)xg; (void)xo;  // consumed next iter via re-load below

            // per-thread poll of the one producer this thread's reload needs
            int fv;
            do {
                asm volatile("ld.acquire.gpu.global.b32 %0, [%1];"
                             : "=r"(fv) : "l"(depflag) : "memory");
            } while (fv < target);

            // reload h(t): this thread's 8 floats (producer confirmed done)
            const float* src = hsrc + (size_t)t * (8 * HDIM);
            float4 v0 = *(const float4*)src;
            float4 v1 = *(const float4*)(src + 4);
            *(float4*)&hsm[warp * 256 + lane * 8]     = v0;
            *(float4*)&hsm[warp * 256 + lane * 8 + 4] = v1;
            __syncthreads();                      // hsm complete
        }
    }
}

// =====================================================================
// Kernel 3: emissions (unchanged)
// =====================================================================
__global__ void emis_kernel(const int* __restrict__ lengths,
                            const float* __restrict__ W_out,
                            const float* __restrict__ b_out)
{
    __shared__ float Wsm[KTAG * 2 * HDIM];
    __shared__ float bsm[KTAG];

    const int tid = threadIdx.x;
    for (int i = tid; i < KTAG * 2 * HDIM; i += 256) Wsm[i] = W_out[i];
    if (tid < KTAG) bsm[tid] = b_out[tid];
    __syncthreads();

    const int warp = tid >> 5;
    const int lane = tid & 31;
    const int r = blockIdx.x * 8 + warp;
    const int b = r >> 9;
    const int t = r & 511;
    const int len = lengths[b];
    const int tr  = (t < len) ? (len - 1 - t) : t;
    const int bt = b >> 3, b_l = b & 7;

    const float* hf = g_h + ((size_t)(0 * 8 + bt)) * (TT * 8 * HDIM)
                          + (size_t)t  * (8 * HDIM) + b_l * HDIM;
    const float* hb = g_h + ((size_t)(1 * 8 + bt)) * (TT * 8 * HDIM)
                          + (size_t)tr * (8 * HDIM) + b_l * HDIM;

    float x[16];
#pragma unroll
    for (int i = 0; i < 8; i++) x[i]     = hf[lane + 32 * i];
#pragma unroll
    for (int i = 0; i < 8; i++) x[8 + i] = hb[lane + 32 * i];

    for (int kk = 0; kk < KTAG; kk++) {
        const float* w = Wsm + (size_t)kk * (2 * HDIM);
        float s = 0.f;
#pragma unroll
        for (int i = 0; i < 8; i++) s += x[i]     * w[lane + 32 * i];
#pragma unroll
        for (int i = 0; i < 8; i++) s += x[8 + i] * w[HDIM + lane + 32 * i];
#pragma unroll
        for (int off = 16; off; off >>= 1) s += __shfl_xor_sync(0xffffffffu, s, off);
        if (lane == 0) g_emis[((size_t)b * TT + t) * KTAG + kk] = s + bsm[kk];
    }
}

// =====================================================================
// Kernel 4: Viterbi — register delta + shfl gather, no smem round-trip
// on the DP chain. First-max semantics preserved (in-order tree,
// keep-left-on-tie).
// =====================================================================
#define VIT_SMEM 53248
#define VCOMB(av, ai_, bv, bi_) { if ((bv) > (av)) { (av) = (bv); (ai_) = (bi_); } }

__global__ void viterbi_kernel(const int* __restrict__ lengths,
                               const int* __restrict__ stop_id_p,
                               const float* __restrict__ trans,
                               float* __restrict__ out)
{
    extern __shared__ char vsm[];
    float* emis_s = (float*)vsm;                 // TT*KTAG
    float* trp    = emis_s + TT * KTAG;          // [KTAG][21]
    float* term   = trp + KTAG * 21;             // KTAG
    unsigned char* bp = (unsigned char*)(term + KTAG);

    const int b = blockIdx.x;
    const int lane = threadIdx.x;

    for (int i = lane; i < TT * KTAG; i += 32)
        emis_s[i] = g_emis[(size_t)b * TT * KTAG + i];
    for (int i = lane; i < KTAG * KTAG; i += 32)
        trp[(i / KTAG) * 21 + (i % KTAG)] = trans[i];
    __syncwarp();

    const int len  = lengths[b];
    const int stop = *stop_id_p;
    const float* trl = trp + (lane < KTAG ? lane : 0) * 21;

    float d = 0.f;    // delta[lane] in register (lanes >= KTAG: dummy)

    for (int t = 0; t < TT; t++) {
        float em = (lane < KTAG) ? emis_s[t * KTAG + lane] : 0.f;

        float v[KTAG];
#pragma unroll
        for (int p = 0; p < KTAG; p++)
            v[p] = __shfl_sync(0xffffffffu, d, p) + trl[p];

        float w10[10]; int i10[10];
#pragma unroll
        for (int i = 0; i < 10; i++) {
            w10[i] = v[2 * i]; i10[i] = 2 * i;
            VCOMB(w10[i], i10[i], v[2 * i + 1], 2 * i + 1);
        }
        float w5[5]; int i5[5];
#pragma unroll
        for (int i = 0; i < 5; i++) {
            w5[i] = w10[2 * i]; i5[i] = i10[2 * i];
            VCOMB(w5[i], i5[i], w10[2 * i + 1], i10[2 * i + 1]);
        }
        float bv0 = w5[0]; int bi0 = i5[0];
        VCOMB(bv0, bi0, w5[1], i5[1]);
        float bv1 = w5[2]; int bi1 = i5[2];
        VCOMB(bv1, bi1, w5[3], i5[3]);
        VCOMB(bv0, bi0, bv1, bi1);
        VCOMB(bv0, bi0, w5[4], i5[4]);

        bool valid = (t < len);
        if (lane < KTAG) {
            float nd = bv0 + em;
            int bpv  = valid ? bi0 : lane;
            d = valid ? nd : d;
            bp[t * KTAG + lane] = (unsigned char)bpv;
        }
    }

    if (lane < KTAG) term[lane] = d + trp[stop * 21 + lane];
    __syncwarp();

    if (lane == 0) {
        float best = -3.4e38f; int arg = 0;
        for (int j = 0; j < KTAG; j++)
            if (term[j] > best) { best = term[j]; arg = j; }
        out[b] = best;
        float* po = out + BB + (size_t)b * (TT + 1);
        po[TT] = (float)arg;
        int tag = arg;
        for (int t = TT - 1; t >= 0; t--) {
            tag = bp[t * KTAG + tag];
            po[t] = (float)tag;
        }
    }
}

// =====================================================================
// launch
// =====================================================================
extern "C" void kernel_launch(void* const* d_in, const int* in_sizes, int n_in,
                              void* d_out, int out_size)
{
    (void)in_sizes; (void)n_in; (void)out_size;
    const int*   sentence = (const int*)d_in[0];
    const int*   lengths  = (const int*)d_in[1];
    const int*   stop_id  = (const int*)d_in[3];
    const float* emb      = (const float*)d_in[4];
    const float* Wf_ih    = (const float*)d_in[5];
    const float* Wf_hh    = (const float*)d_in[6];
    const float* bf       = (const float*)d_in[7];
    const float* Wb_ih    = (const float*)d_in[8];
    const float* Wb_hh    = (const float*)d_in[9];
    const float* bb       = (const float*)d_in[10];
    const float* W_out    = (const float*)d_in[11];
    const float* b_out    = (const float*)d_in[12];
    const float* trans    = (const float*)d_in[13];
    float* out = (float*)d_out;

    static int attr_set = 0;
    if (!attr_set) {
        cudaFuncSetAttribute(lstm_persistent_kernel,
                             cudaFuncAttributeMaxDynamicSharedMemorySize, SMEM_LSTM);
        cudaFuncSetAttribute(viterbi_kernel,
                             cudaFuncAttributeMaxDynamicSharedMemorySize, VIT_SMEM);
        attr_set = 1;
    }

    dim3 g1(BB * TT / BM, G4 / BN, 2);
    gates_gemm_kernel<<<g1, 256>>>(sentence, lengths, emb, Wf_ih, bf, Wb_ih, bb);

    lstm_persistent_kernel<<<GRID_P, 256, SMEM_LSTM>>>(Wf_hh, Wb_hh);

    emis_kernel<<<BB * TT / 8, 256>>>(lengths, W_out, b_out);

    viterbi_kernel<<<BB, 32, VIT_SMEM>>>(lengths, stop_id, trans, out);
}

// round 9
// speedup vs baseline: 1.7359x; 1.0244x over previous
#include <cuda_runtime.h>
#include <math.h>

// Problem constants
#define BB   64
#define TT   512
#define EE   300
#define HDIM 256
#define G4   1024
#define KTAG 20
#define GRID_P 128

typedef unsigned long long ull;

// ---------------- scratch ----------------
// g_X blocked: [dir][bt][ks][t][b_l][gate][k_l]
__device__ float g_X[(size_t)2 * BB * TT * G4];
// g_h blocked: [dir][bt][t][b_l][k]
__device__ float g_h[(size_t)2 * BB * TT * HDIM];
__device__ float g_emis[(size_t)BB * TT * KTAG];
__device__ int   g_flagsA[16 * 8 * 32];

// ---------------- packed fp32x2 helpers ----------------
__device__ __forceinline__ ull ffma2(ull a, ull b, ull c) {
    ull d;
    asm("fma.rn.f32x2 %0, %1, %2, %3;" : "=l"(d) : "l"(a), "l"(b), "l"(c));
    return d;
}
__device__ __forceinline__ ull f2u2(float x, float y) {
    ull v;
    asm("mov.b64 %0, {%1, %2};" : "=l"(v) : "f"(x), "f"(y));
    return v;
}
__device__ __forceinline__ float2 u2f2(ull v) {
    float2 f;
    asm("mov.b64 {%0, %1}, %2;" : "=f"(f.x), "=f"(f.y) : "l"(v));
    return f;
}

#define BARL() asm volatile("bar.sync 4, 256;" ::: "memory")
#define BARG() asm volatile("bar.sync 5, 128;" ::: "memory")

__device__ __forceinline__ float sigf(float x) { return 1.f / (1.f + expf(-x)); }

// =====================================================================
// FUSED persistent kernel: 128 CTAs x 384 threads.
//   warps 0-7  : LSTM (identical structure to R8)
//   warps 8-11 : gates GEMM producing this CTA's own X blocks, t-ordered,
//                publishing progress via smem xprog (release/acquire cta)
// =====================================================================
#define WP_ULL (4 * 128 * 33)
// smem: Wp 135168B | hsm 8192B | ps 32768B | As 4608B | Bs 4352B | tok 256B | xprog 128B
#define SMEM_FUSED 185472

__global__ void __launch_bounds__(384, 1)
fused_persistent_kernel(const int* __restrict__ sentence,
                        const int* __restrict__ lengths,
                        const float* __restrict__ emb,
                        const float* __restrict__ Wf_ih,
                        const float* __restrict__ bf,
                        const float* __restrict__ Wb_ih,
                        const float* __restrict__ bb,
                        const float* __restrict__ Wf_hh,
                        const float* __restrict__ Wb_hh)
{
    extern __shared__ char smraw[];
    ull*   Wp   = (ull*)smraw;                   // [4][128][33]
    float* hsm  = (float*)(Wp + WP_ULL);         // [8][256]
    float* ps   = hsm + 2048;                    // [8][4][8][32]
    float* As   = ps + 8192;                     // [16][72]
    float* Bs   = As + 16 * 72;                  // [16][68]
    int*   tok2 = (int*)(Bs + 16 * 68);          // [64]
    int*   xprog = tok2 + 64;
    ull*   hsmu = (ull*)hsm;

    const int bx  = blockIdx.x;
    const int dir = bx & 1;
    const int ks  = (bx >> 1) & 7;
    const int bt  = bx >> 4;
    const int k0s = ks * 32;
    const int b0  = bt * 8;
    const int tid = threadIdx.x;
    const int grp = bt * 2 + dir;

    const float* __restrict__ Whh  = dir ? Wb_hh : Wf_hh;
    const float* __restrict__ Wih  = dir ? Wb_ih : Wf_ih;
    const float* __restrict__ bias = dir ? bb    : bf;

    int* myflag = &g_flagsA[(grp * 8 + ks) * 32];
    int base = 0;

    if (tid < 256) {
        // pack W_hh slice transposed into smem
        for (int i = tid; i < 128 * 128; i += 256) {
            int r = i >> 7;
            int j = i & 127;
            int g = r >> 5, kl = r & 31;
            ull v = *(const ull*)(Whh + (size_t)(g * 256 + k0s + kl) * HDIM + 2 * j);
            Wp[(g * 128 + j) * 33 + kl] = v;
        }
        for (int i = tid; i < 2048; i += 256) hsm[i] = 0.f;
        base = *(volatile int*)myflag;
    } else {
        if (tid == 256) *xprog = 0;
    }
    __syncthreads();   // single full-block sync; after this, halves never share barriers

    if (tid < 256) {
        // ================= LSTM half =================
        const int lane = tid & 31;
        const int warp = tid >> 5;
        const int b2   = warp;

        int* depflag = &g_flagsA[(grp * 8 + (lane >> 2)) * 32];

        const float* xme = g_X + ((size_t)((dir * 8 + bt) * 8 + ks)) * (TT * 1024)
                               + b2 * 128 + lane;
        float* hme = g_h + ((size_t)(dir * 8 + bt)) * (TT * 8 * HDIM)
                         + b2 * HDIM + (k0s + lane);
        const float* hsrc = g_h + ((size_t)(dir * 8 + bt)) * (TT * 8 * HDIM)
                                + warp * HDIM + lane * 8;
        const int kkb = warp * 16;

        float c_st = 0.f;

        for (int t = 0; t < TT; t++) {
            // wait until this CTA's GEMM warps have produced X(t)
            int xv;
            do {
                asm volatile("ld.acquire.cta.b32 %0, [%1];" : "=r"(xv) : "l"(xprog) : "memory");
            } while (xv < t + 1);

            const float* xr = xme + (size_t)t * 1024;
            float xi = xr[0], xf = xr[32], xg = xr[64], xo = xr[96];

            ull acc[4][8];
#pragma unroll
            for (int g = 0; g < 4; g++)
#pragma unroll
                for (int b = 0; b < 8; b++) acc[g][b] = 0ull;

#pragma unroll 4
            for (int c = 0; c < 16; c++) {
                int kk2 = kkb + c;
                ull w0 = Wp[(0 * 128 + kk2) * 33 + lane];
                ull w1 = Wp[(1 * 128 + kk2) * 33 + lane];
                ull w2 = Wp[(2 * 128 + kk2) * 33 + lane];
                ull w3 = Wp[(3 * 128 + kk2) * 33 + lane];
#pragma unroll
                for (int b = 0; b < 8; b++) {
                    ull h2 = hsmu[b * 128 + kk2];
                    acc[0][b] = ffma2(h2, w0, acc[0][b]);
                    acc[1][b] = ffma2(h2, w1, acc[1][b]);
                    acc[2][b] = ffma2(h2, w2, acc[2][b]);
                    acc[3][b] = ffma2(h2, w3, acc[3][b]);
                }
            }

#pragma unroll
            for (int g = 0; g < 4; g++)
#pragma unroll
                for (int b = 0; b < 8; b++) {
                    float2 s = u2f2(acc[g][b]);
                    ps[((warp * 4 + g) * 8 + b) * 32 + lane] = s.x + s.y;
                }
            BARL();

            float s0 = 0.f, s1 = 0.f, s2 = 0.f, s3 = 0.f;
#pragma unroll
            for (int w = 0; w < 8; w++) {
                s0 += ps[((w * 4 + 0) * 8 + b2) * 32 + lane];
                s1 += ps[((w * 4 + 1) * 8 + b2) * 32 + lane];
                s2 += ps[((w * 4 + 2) * 8 + b2) * 32 + lane];
                s3 += ps[((w * 4 + 3) * 8 + b2) * 32 + lane];
            }
            float gi = xi + s0;
            float gf = xf + s1;
            float gg = xg + s2;
            float go = xo + s3;

            c_st = sigf(gf) * c_st + sigf(gi) * tanhf(gg);
            float hn = sigf(go) * tanhf(c_st);
            hme[(size_t)t * (8 * HDIM)] = hn;

            if (t + 1 < TT) {
                const int target = base + t + 1;
                BARL();                            // h STGs issued; psum reads done
                if (tid == 0) {
                    asm volatile("st.release.gpu.global.b32 [%0], %1;"
                                 :: "l"(myflag), "r"(target) : "memory");
                }
                int fv;
                do {
                    asm volatile("ld.acquire.gpu.global.b32 %0, [%1];"
                                 : "=r"(fv) : "l"(depflag) : "memory");
                } while (fv < target);

                const float* src = hsrc + (size_t)t * (8 * HDIM);
                float4 v0 = *(const float4*)src;
                float4 v1 = *(const float4*)(src + 4);
                *(float4*)&hsm[warp * 256 + lane * 8]     = v0;
                *(float4*)&hsm[warp * 256 + lane * 8 + 4] = v1;
                BARL();
            }
        }
    } else {
        // ================= GEMM half (warps 8-11) =================
        const int tid2 = tid - 256;        // 0..127
        const int tx = tid2 & 15;          // n quad
        const int ty = tid2 >> 4;          // m oct
        const int nl = tid2 >> 1;          // load row 0..63
        const int kc = (tid2 & 1) * 8;     // k chunk within 16
        const size_t xbase = ((size_t)((dir * 8 + bt) * 8 + ks)) * (TT * 1024);

        for (int mt = 0; mt < 64; mt++) {
            if (tid2 < 64) {
                int tloc = tid2 >> 3, b_l = tid2 & 7;
                int t = mt * 8 + tloc, b = b0 + b_l;
                int tt = t;
                if (dir) { int len = lengths[b]; tt = (t < len) ? (len - 1 - t) : t; }
                tok2[tid2] = sentence[b * TT + tt];
            }
            BARG();

            for (int nt = 0; nt < 2; nt++) {
                ull acc[4][4];
#pragma unroll
                for (int i = 0; i < 4; i++)
#pragma unroll
                    for (int j = 0; j < 4; j++) acc[i][j] = 0ull;

                const int nglob = nt * 64 + nl;
                const float* wrow = Wih + (size_t)((nglob >> 5) * 256 + k0s + (nglob & 31)) * EE;
                const float* erow = emb + (size_t)tok2[nl] * EE;

                for (int k0 = 0; k0 < 304; k0 += 16) {
                    const int kb = k0 + kc;
                    // A tile (transposed store)
                    if (kb + 8 <= EE) {
                        float4 v0 = *(const float4*)(erow + kb);
                        float4 v1 = *(const float4*)(erow + kb + 4);
                        As[(kc + 0) * 72 + nl] = v0.x;
                        As[(kc + 1) * 72 + nl] = v0.y;
                        As[(kc + 2) * 72 + nl] = v0.z;
                        As[(kc + 3) * 72 + nl] = v0.w;
                        As[(kc + 4) * 72 + nl] = v1.x;
                        As[(kc + 5) * 72 + nl] = v1.y;
                        As[(kc + 6) * 72 + nl] = v1.z;
                        As[(kc + 7) * 72 + nl] = v1.w;
                    } else {
#pragma unroll
                        for (int i = 0; i < 8; i++)
                            As[(kc + i) * 72 + nl] = (kb + i < EE) ? erow[kb + i] : 0.f;
                    }
                    // B tile (transposed store)
                    if (kb + 8 <= EE) {
                        float4 v0 = *(const float4*)(wrow + kb);
                        float4 v1 = *(const float4*)(wrow + kb + 4);
                        Bs[(kc + 0) * 68 + nl] = v0.x;
                        Bs[(kc + 1) * 68 + nl] = v0.y;
                        Bs[(kc + 2) * 68 + nl] = v0.z;
                        Bs[(kc + 3) * 68 + nl] = v0.w;
                        Bs[(kc + 4) * 68 + nl] = v1.x;
                        Bs[(kc + 5) * 68 + nl] = v1.y;
                        Bs[(kc + 6) * 68 + nl] = v1.z;
                        Bs[(kc + 7) * 68 + nl] = v1.w;
                    } else {
#pragma unroll
                        for (int i = 0; i < 8; i++)
                            Bs[(kc + i) * 68 + nl] = (kb + i < EE) ? wrow[kb + i] : 0.f;
                    }
                    BARG();

#pragma unroll
                    for (int kk = 0; kk < 16; kk++) {
                        ulonglong2 a0 = *(const ulonglong2*)&As[kk * 72 + ty * 8];
                        ulonglong2 a1 = *(const ulonglong2*)&As[kk * 72 + ty * 8 + 4];
                        float4 bv = *(const float4*)&Bs[kk * 68 + tx * 4];
                        ull q0 = f2u2(bv.x, bv.x);
                        ull q1 = f2u2(bv.y, bv.y);
                        ull q2 = f2u2(bv.z, bv.z);
                        ull q3 = f2u2(bv.w, bv.w);
                        acc[0][0] = ffma2(a0.x, q0, acc[0][0]);
                        acc[0][1] = ffma2(a0.x, q1, acc[0][1]);
                        acc[0][2] = ffma2(a0.x, q2, acc[0][2]);
                        acc[0][3] = ffma2(a0.x, q3, acc[0][3]);
                        acc[1][0] = ffma2(a0.y, q0, acc[1][0]);
                        acc[1][1] = ffma2(a0.y, q1, acc[1][1]);
                        acc[1][2] = ffma2(a0.y, q2, acc[1][2]);
                        acc[1][3] = ffma2(a0.y, q3, acc[1][3]);
                        acc[2][0] = ffma2(a1.x, q0, acc[2][0]);
                        acc[2][1] = ffma2(a1.x, q1, acc[2][1]);
                        acc[2][2] = ffma2(a1.x, q2, acc[2][2]);
                        acc[2][3] = ffma2(a1.x, q3, acc[2][3]);
                        acc[3][0] = ffma2(a1.y, q0, acc[3][0]);
                        acc[3][1] = ffma2(a1.y, q1, acc[3][1]);
                        acc[3][2] = ffma2(a1.y, q2, acc[3][2]);
                        acc[3][3] = ffma2(a1.y, q3, acc[3][3]);
                    }
                    BARG();
                }

                // epilogue
                const int ng = nt * 64 + tx * 4;
                const float* bp2 = bias + (ng >> 5) * 256 + k0s + (ng & 31);
                float4 bv4;
                bv4.x = bp2[0]; bv4.y = bp2[1]; bv4.z = bp2[2]; bv4.w = bp2[3];
#pragma unroll
                for (int mp = 0; mp < 4; mp++) {
                    float2 c0 = u2f2(acc[mp][0]);
                    float2 c1 = u2f2(acc[mp][1]);
                    float2 c2 = u2f2(acc[mp][2]);
                    float2 c3 = u2f2(acc[mp][3]);
#pragma unroll
                    for (int h = 0; h < 2; h++) {
                        int m = ty * 8 + 2 * mp + h;
                        int tloc = m >> 3, b_l = m & 7;
                        size_t off = xbase + (size_t)(mt * 8 + tloc) * 1024 + b_l * 128 + ng;
                        float4 v;
                        if (h == 0) { v.x = c0.x + bv4.x; v.y = c1.x + bv4.y; v.z = c2.x + bv4.z; v.w = c3.x + bv4.w; }
                        else        { v.x = c0.y + bv4.x; v.y = c1.y + bv4.y; v.z = c2.y + bv4.z; v.w = c3.y + bv4.w; }
                        *(float4*)&g_X[off] = v;
                    }
                }
            }
            BARG();   // all X stores for this mt issued by all 4 warps
            if (tid2 == 0) {
                int val = (mt + 1) * 8;
                asm volatile("st.release.cta.b32 [%0], %1;" :: "l"(xprog), "r"(val) : "memory");
            }
        }
    }
}

// =====================================================================
// Kernel 3: emissions (unchanged)
// =====================================================================
__global__ void emis_kernel(const int* __restrict__ lengths,
                            const float* __restrict__ W_out,
                            const float* __restrict__ b_out)
{
    __shared__ float Wsm[KTAG * 2 * HDIM];
    __shared__ float bsm[KTAG];

    const int tid = threadIdx.x;
    for (int i = tid; i < KTAG * 2 * HDIM; i += 256) Wsm[i] = W_out[i];
    if (tid < KTAG) bsm[tid] = b_out[tid];
    __syncthreads();

    const int warp = tid >> 5;
    const int lane = tid & 31;
    const int r = blockIdx.x * 8 + warp;
    const int b = r >> 9;
    const int t = r & 511;
    const int len = lengths[b];
    const int tr  = (t < len) ? (len - 1 - t) : t;
    const int bt = b >> 3, b_l = b & 7;

    const float* hf = g_h + ((size_t)(0 * 8 + bt)) * (TT * 8 * HDIM)
                          + (size_t)t  * (8 * HDIM) + b_l * HDIM;
    const float* hb = g_h + ((size_t)(1 * 8 + bt)) * (TT * 8 * HDIM)
                          + (size_t)tr * (8 * HDIM) + b_l * HDIM;

    float x[16];
#pragma unroll
    for (int i = 0; i < 8; i++) x[i]     = hf[lane + 32 * i];
#pragma unroll
    for (int i = 0; i < 8; i++) x[8 + i] = hb[lane + 32 * i];

    for (int kk = 0; kk < KTAG; kk++) {
        const float* w = Wsm + (size_t)kk * (2 * HDIM);
        float s = 0.f;
#pragma unroll
        for (int i = 0; i < 8; i++) s += x[i]     * w[lane + 32 * i];
#pragma unroll
        for (int i = 0; i < 8; i++) s += x[8 + i] * w[HDIM + lane + 32 * i];
#pragma unroll
        for (int off = 16; off; off >>= 1) s += __shfl_xor_sync(0xffffffffu, s, off);
        if (lane == 0) g_emis[((size_t)b * TT + t) * KTAG + kk] = s + bsm[kk];
    }
}

// =====================================================================
// Kernel 4: Viterbi (unchanged from R8)
// =====================================================================
#define VIT_SMEM 53248
#define VCOMB(av, ai_, bv, bi_) { if ((bv) > (av)) { (av) = (bv); (ai_) = (bi_); } }

__global__ void viterbi_kernel(const int* __restrict__ lengths,
                               const int* __restrict__ stop_id_p,
                               const float* __restrict__ trans,
                               float* __restrict__ out)
{
    extern __shared__ char vsm[];
    float* emis_s = (float*)vsm;
    float* trp    = emis_s + TT * KTAG;
    float* term   = trp + KTAG * 21;
    unsigned char* bp = (unsigned char*)(term + KTAG);

    const int b = blockIdx.x;
    const int lane = threadIdx.x;

    for (int i = lane; i < TT * KTAG; i += 32)
        emis_s[i] = g_emis[(size_t)b * TT * KTAG + i];
    for (int i = lane; i < KTAG * KTAG; i += 32)
        trp[(i / KTAG) * 21 + (i % KTAG)] = trans[i];
    __syncwarp();

    const int len  = lengths[b];
    const int stop = *stop_id_p;
    const float* trl = trp + (lane < KTAG ? lane : 0) * 21;

    float d = 0.f;

    for (int t = 0; t < TT; t++) {
        float em = (lane < KTAG) ? emis_s[t * KTAG + lane] : 0.f;

        float v[KTAG];
#pragma unroll
        for (int p = 0; p < KTAG; p++)
            v[p] = __shfl_sync(0xffffffffu, d, p) + trl[p];

        float w10[10]; int i10[10];
#pragma unroll
        for (int i = 0; i < 10; i++) {
            w10[i] = v[2 * i]; i10[i] = 2 * i;
            VCOMB(w10[i], i10[i], v[2 * i + 1], 2 * i + 1);
        }
        float w5[5]; int i5[5];
#pragma unroll
        for (int i = 0; i < 5; i++) {
            w5[i] = w10[2 * i]; i5[i] = i10[2 * i];
            VCOMB(w5[i], i5[i], w10[2 * i + 1], i10[2 * i + 1]);
        }
        float bv0 = w5[0]; int bi0 = i5[0];
        VCOMB(bv0, bi0, w5[1], i5[1]);
        float bv1 = w5[2]; int bi1 = i5[2];
        VCOMB(bv1, bi1, w5[3], i5[3]);
        VCOMB(bv0, bi0, bv1, bi1);
        VCOMB(bv0, bi0, w5[4], i5[4]);

        bool valid = (t < len);
        if (lane < KTAG) {
            float nd = bv0 + em;
            int bpv  = valid ? bi0 : lane;
            d = valid ? nd : d;
            bp[t * KTAG + lane] = (unsigned char)bpv;
        }
    }

    if (lane < KTAG) term[lane] = d + trp[stop * 21 + lane];
    __syncwarp();

    if (lane == 0) {
        float best = -3.4e38f; int arg = 0;
        for (int j = 0; j < KTAG; j++)
            if (term[j] > best) { best = term[j]; arg = j; }
        out[b] = best;
        float* po = out + BB + (size_t)b * (TT + 1);
        po[TT] = (float)arg;
        int tag = arg;
        for (int t = TT - 1; t >= 0; t--) {
            tag = bp[t * KTAG + tag];
            po[t] = (float)tag;
        }
    }
}

// =====================================================================
// launch
// =====================================================================
extern "C" void kernel_launch(void* const* d_in, const int* in_sizes, int n_in,
                              void* d_out, int out_size)
{
    (void)in_sizes; (void)n_in; (void)out_size;
    const int*   sentence = (const int*)d_in[0];
    const int*   lengths  = (const int*)d_in[1];
    const int*   stop_id  = (const int*)d_in[3];
    const float* emb      = (const float*)d_in[4];
    const float* Wf_ih    = (const float*)d_in[5];
    const float* Wf_hh    = (const float*)d_in[6];
    const float* bf       = (const float*)d_in[7];
    const float* Wb_ih    = (const float*)d_in[8];
    const float* Wb_hh    = (const float*)d_in[9];
    const float* bb       = (const float*)d_in[10];
    const float* W_out    = (const float*)d_in[11];
    const float* b_out    = (const float*)d_in[12];
    const float* trans    = (const float*)d_in[13];
    float* out = (float*)d_out;

    static int attr_set = 0;
    if (!attr_set) {
        cudaFuncSetAttribute(fused_persistent_kernel,
                             cudaFuncAttributeMaxDynamicSharedMemorySize, SMEM_FUSED);
        cudaFuncSetAttribute(viterbi_kernel,
                             cudaFuncAttributeMaxDynamicSharedMemorySize, VIT_SMEM);
        attr_set = 1;
    }

    fused_persistent_kernel<<<GRID_P, 384, SMEM_FUSED>>>(
        sentence, lengths, emb, Wf_ih, bf, Wb_ih, bb, Wf_hh, Wb_hh);

    emis_kernel<<<BB * TT / 8, 256>>>(lengths, W_out, b_out);

    viterbi_kernel<<<BB, 32, VIT_SMEM>>>(lengths, stop_id, trans, out);
}

// round 10
// speedup vs baseline: 1.8303x; 1.0543x over previous
#include <cuda_runtime.h>
#include <math.h>

// Problem constants
#define BB   64
#define TT   512
#define EE   300
#define HDIM 256
#define G4   1024
#define KTAG 20
#define GRID_P 128

typedef unsigned long long ull;

// ---------------- scratch ----------------
// g_X blocked: [dir][bt][ks][t][b_l][gate][k_l]
__device__ float g_X[(size_t)2 * BB * TT * G4];
// g_h blocked: [dir][bt][t][b_l][k]
__device__ float g_h[(size_t)2 * BB * TT * HDIM];
__device__ float g_emis[(size_t)BB * TT * KTAG];
__device__ int   g_flagsA[16 * 8 * 32];

// ---------------- packed fp32x2 helpers ----------------
__device__ __forceinline__ ull ffma2(ull a, ull b, ull c) {
    ull d;
    asm("fma.rn.f32x2 %0, %1, %2, %3;" : "=l"(d) : "l"(a), "l"(b), "l"(c));
    return d;
}
__device__ __forceinline__ ull f2u2(float x, float y) {
    ull v;
    asm("mov.b64 %0, {%1, %2};" : "=l"(v) : "f"(x), "f"(y));
    return v;
}
__device__ __forceinline__ float2 u2f2(ull v) {
    float2 f;
    asm("mov.b64 {%0, %1}, %2;" : "=f"(f.x), "=f"(f.y) : "l"(v));
    return f;
}

#define BARL() asm volatile("bar.sync 4, 256;" ::: "memory")
#define BARG() asm volatile("bar.sync 5, 128;" ::: "memory")

__device__ __forceinline__ float sigf(float x) { return 1.f / (1.f + expf(-x)); }

// =====================================================================
// FUSED persistent kernel: 128 CTAs x 384 threads.
//   warps 0-3  : gates GEMM (LOW wid -> low arbiter priority, fills idle)
//   warps 4-11 : LSTM (HIGH wid -> wins issue slots on its critical path)
// =====================================================================
#define WP_ULL (4 * 128 * 33)
#define SMEM_FUSED 185472

__global__ void __launch_bounds__(384, 1)
fused_persistent_kernel(const int* __restrict__ sentence,
                        const int* __restrict__ lengths,
                        const float* __restrict__ emb,
                        const float* __restrict__ Wf_ih,
                        const float* __restrict__ bf,
                        const float* __restrict__ Wb_ih,
                        const float* __restrict__ bb,
                        const float* __restrict__ Wf_hh,
                        const float* __restrict__ Wb_hh)
{
    extern __shared__ char smraw[];
    ull*   Wp   = (ull*)smraw;                   // [4][128][33]
    float* hsm  = (float*)(Wp + WP_ULL);         // [8][256]
    float* ps   = hsm + 2048;                    // [8][4][8][32]
    float* As   = ps + 8192;                     // [16][72]
    float* Bs   = As + 16 * 72;                  // [16][68]
    int*   tok2 = (int*)(Bs + 16 * 68);          // [64]
    int*   xprog = tok2 + 64;
    ull*   hsmu = (ull*)hsm;

    const int bx  = blockIdx.x;
    const int dir = bx & 1;
    const int ks  = (bx >> 1) & 7;
    const int bt  = bx >> 4;
    const int k0s = ks * 32;
    const int b0  = bt * 8;
    const int tid = threadIdx.x;
    const int grp = bt * 2 + dir;

    const float* __restrict__ Whh  = dir ? Wb_hh : Wf_hh;
    const float* __restrict__ Wih  = dir ? Wb_ih : Wf_ih;
    const float* __restrict__ bias = dir ? bb    : bf;

    int* myflag = &g_flagsA[(grp * 8 + ks) * 32];

    // all threads cooperate on one-time init
    for (int i = tid; i < 128 * 128; i += 384) {
        int r = i >> 7;
        int j = i & 127;
        int g = r >> 5, kl = r & 31;
        ull v = *(const ull*)(Whh + (size_t)(g * 256 + k0s + kl) * HDIM + 2 * j);
        Wp[(g * 128 + j) * 33 + kl] = v;
    }
    for (int i = tid; i < 2048; i += 384) hsm[i] = 0.f;
    if (tid == 0) *xprog = 0;
    const int base = *(volatile int*)myflag;
    __syncthreads();   // single full-block sync; halves never share barriers after

    if (tid >= 128) {
        // ================= LSTM half (warps 4-11, HIGH priority) =========
        const int ltid = tid - 128;        // 0..255
        const int lane = ltid & 31;
        const int warp = ltid >> 5;        // 0..7
        const int b2   = warp;

        int* depflag = &g_flagsA[(grp * 8 + (lane >> 2)) * 32];

        const float* xme = g_X + ((size_t)((dir * 8 + bt) * 8 + ks)) * (TT * 1024)
                               + b2 * 128 + lane;
        float* hme = g_h + ((size_t)(dir * 8 + bt)) * (TT * 8 * HDIM)
                         + b2 * HDIM + (k0s + lane);
        const float* hsrc = g_h + ((size_t)(dir * 8 + bt)) * (TT * 8 * HDIM)
                                + warp * HDIM + lane * 8;
        const int kkb = warp * 16;

        float c_st = 0.f;

        for (int t = 0; t < TT; t++) {
            // wait until this CTA's GEMM warps have produced X(t)
            int xv;
            do {
                asm volatile("ld.acquire.cta.b32 %0, [%1];" : "=r"(xv) : "l"(xprog) : "memory");
            } while (xv < t + 1);

            const float* xr = xme + (size_t)t * 1024;
            float xi = xr[0], xf = xr[32], xg = xr[64], xo = xr[96];

            ull acc[4][8];
#pragma unroll
            for (int g = 0; g < 4; g++)
#pragma unroll
                for (int b = 0; b < 8; b++) acc[g][b] = 0ull;

#pragma unroll 4
            for (int c = 0; c < 16; c++) {
                int kk2 = kkb + c;
                ull w0 = Wp[(0 * 128 + kk2) * 33 + lane];
                ull w1 = Wp[(1 * 128 + kk2) * 33 + lane];
                ull w2 = Wp[(2 * 128 + kk2) * 33 + lane];
                ull w3 = Wp[(3 * 128 + kk2) * 33 + lane];
#pragma unroll
                for (int b = 0; b < 8; b++) {
                    ull h2 = hsmu[b * 128 + kk2];
                    acc[0][b] = ffma2(h2, w0, acc[0][b]);
                    acc[1][b] = ffma2(h2, w1, acc[1][b]);
                    acc[2][b] = ffma2(h2, w2, acc[2][b]);
                    acc[3][b] = ffma2(h2, w3, acc[3][b]);
                }
            }

#pragma unroll
            for (int g = 0; g < 4; g++)
#pragma unroll
                for (int b = 0; b < 8; b++) {
                    float2 s = u2f2(acc[g][b]);
                    ps[((warp * 4 + g) * 8 + b) * 32 + lane] = s.x + s.y;
                }
            BARL();

            float s0 = 0.f, s1 = 0.f, s2 = 0.f, s3 = 0.f;
#pragma unroll
            for (int w = 0; w < 8; w++) {
                s0 += ps[((w * 4 + 0) * 8 + b2) * 32 + lane];
                s1 += ps[((w * 4 + 1) * 8 + b2) * 32 + lane];
                s2 += ps[((w * 4 + 2) * 8 + b2) * 32 + lane];
                s3 += ps[((w * 4 + 3) * 8 + b2) * 32 + lane];
            }
            float gi = xi + s0;
            float gf = xf + s1;
            float gg = xg + s2;
            float go = xo + s3;

            c_st = sigf(gf) * c_st + sigf(gi) * tanhf(gg);
            float hn = sigf(go) * tanhf(c_st);
            hme[(size_t)t * (8 * HDIM)] = hn;

            if (t + 1 < TT) {
                const int target = base + t + 1;
                BARL();                            // h STGs issued; psum reads done
                if (ltid == 0) {
                    asm volatile("st.release.gpu.global.b32 [%0], %1;"
                                 :: "l"(myflag), "r"(target) : "memory");
                }
                int fv;
                do {
                    asm volatile("ld.acquire.gpu.global.b32 %0, [%1];"
                                 : "=r"(fv) : "l"(depflag) : "memory");
                } while (fv < target);

                const float* src = hsrc + (size_t)t * (8 * HDIM);
                float4 v0 = *(const float4*)src;
                float4 v1 = *(const float4*)(src + 4);
                *(float4*)&hsm[warp * 256 + lane * 8]     = v0;
                *(float4*)&hsm[warp * 256 + lane * 8 + 4] = v1;
                BARL();
            }
        }
    } else {
        // ================= GEMM half (warps 0-3, LOW priority) ===========
        const int tid2 = tid;              // 0..127
        const int tx = tid2 & 15;          // n quad
        const int ty = tid2 >> 4;          // m oct
        const int nl = tid2 >> 1;          // load row 0..63
        const int kc = (tid2 & 1) * 8;     // k chunk within 16
        const size_t xbase = ((size_t)((dir * 8 + bt) * 8 + ks)) * (TT * 1024);

        for (int mt = 0; mt < 64; mt++) {
            if (tid2 < 64) {
                int tloc = tid2 >> 3, b_l = tid2 & 7;
                int t = mt * 8 + tloc, b = b0 + b_l;
                int tt = t;
                if (dir) { int len = lengths[b]; tt = (t < len) ? (len - 1 - t) : t; }
                tok2[tid2] = sentence[b * TT + tt];
            }
            BARG();

            for (int nt = 0; nt < 2; nt++) {
                ull acc[4][4];
#pragma unroll
                for (int i = 0; i < 4; i++)
#pragma unroll
                    for (int j = 0; j < 4; j++) acc[i][j] = 0ull;

                const int nglob = nt * 64 + nl;
                const float* wrow = Wih + (size_t)((nglob >> 5) * 256 + k0s + (nglob & 31)) * EE;
                const float* erow = emb + (size_t)tok2[nl] * EE;

                for (int k0 = 0; k0 < 304; k0 += 16) {
                    const int kb = k0 + kc;
                    if (kb + 8 <= EE) {
                        float4 v0 = *(const float4*)(erow + kb);
                        float4 v1 = *(const float4*)(erow + kb + 4);
                        As[(kc + 0) * 72 + nl] = v0.x;
                        As[(kc + 1) * 72 + nl] = v0.y;
                        As[(kc + 2) * 72 + nl] = v0.z;
                        As[(kc + 3) * 72 + nl] = v0.w;
                        As[(kc + 4) * 72 + nl] = v1.x;
                        As[(kc + 5) * 72 + nl] = v1.y;
                        As[(kc + 6) * 72 + nl] = v1.z;
                        As[(kc + 7) * 72 + nl] = v1.w;
                    } else {
#pragma unroll
                        for (int i = 0; i < 8; i++)
                            As[(kc + i) * 72 + nl] = (kb + i < EE) ? erow[kb + i] : 0.f;
                    }
                    if (kb + 8 <= EE) {
                        float4 v0 = *(const float4*)(wrow + kb);
                        float4 v1 = *(const float4*)(wrow + kb + 4);
                        Bs[(kc + 0) * 68 + nl] = v0.x;
                        Bs[(kc + 1) * 68 + nl] = v0.y;
                        Bs[(kc + 2) * 68 + nl] = v0.z;
                        Bs[(kc + 3) * 68 + nl] = v0.w;
                        Bs[(kc + 4) * 68 + nl] = v1.x;
                        Bs[(kc + 5) * 68 + nl] = v1.y;
                        Bs[(kc + 6) * 68 + nl] = v1.z;
                        Bs[(kc + 7) * 68 + nl] = v1.w;
                    } else {
#pragma unroll
                        for (int i = 0; i < 8; i++)
                            Bs[(kc + i) * 68 + nl] = (kb + i < EE) ? wrow[kb + i] : 0.f;
                    }
                    BARG();

#pragma unroll
                    for (int kk = 0; kk < 16; kk++) {
                        ulonglong2 a0 = *(const ulonglong2*)&As[kk * 72 + ty * 8];
                        ulonglong2 a1 = *(const ulonglong2*)&As[kk * 72 + ty * 8 + 4];
                        float4 bv = *(const float4*)&Bs[kk * 68 + tx * 4];
                        ull q0 = f2u2(bv.x, bv.x);
                        ull q1 = f2u2(bv.y, bv.y);
                        ull q2 = f2u2(bv.z, bv.z);
                        ull q3 = f2u2(bv.w, bv.w);
                        acc[0][0] = ffma2(a0.x, q0, acc[0][0]);
                        acc[0][1] = ffma2(a0.x, q1, acc[0][1]);
                        acc[0][2] = ffma2(a0.x, q2, acc[0][2]);
                        acc[0][3] = ffma2(a0.x, q3, acc[0][3]);
                        acc[1][0] = ffma2(a0.y, q0, acc[1][0]);
                        acc[1][1] = ffma2(a0.y, q1, acc[1][1]);
                        acc[1][2] = ffma2(a0.y, q2, acc[1][2]);
                        acc[1][3] = ffma2(a0.y, q3, acc[1][3]);
                        acc[2][0] = ffma2(a1.x, q0, acc[2][0]);
                        acc[2][1] = ffma2(a1.x, q1, acc[2][1]);
                        acc[2][2] = ffma2(a1.x, q2, acc[2][2]);
                        acc[2][3] = ffma2(a1.x, q3, acc[2][3]);
                        acc[3][0] = ffma2(a1.y, q0, acc[3][0]);
                        acc[3][1] = ffma2(a1.y, q1, acc[3][1]);
                        acc[3][2] = ffma2(a1.y, q2, acc[3][2]);
                        acc[3][3] = ffma2(a1.y, q3, acc[3][3]);
                    }
                    BARG();
                }

                const int ng = nt * 64 + tx * 4;
                const float* bp2 = bias + (ng >> 5) * 256 + k0s + (ng & 31);
                float4 bv4;
                bv4.x = bp2[0]; bv4.y = bp2[1]; bv4.z = bp2[2]; bv4.w = bp2[3];
#pragma unroll
                for (int mp = 0; mp < 4; mp++) {
                    float2 c0 = u2f2(acc[mp][0]);
                    float2 c1 = u2f2(acc[mp][1]);
                    float2 c2 = u2f2(acc[mp][2]);
                    float2 c3 = u2f2(acc[mp][3]);
#pragma unroll
                    for (int h = 0; h < 2; h++) {
                        int m = ty * 8 + 2 * mp + h;
                        int tloc = m >> 3, b_l = m & 7;
                        size_t off = xbase + (size_t)(mt * 8 + tloc) * 1024 + b_l * 128 + ng;
                        float4 v;
                        if (h == 0) { v.x = c0.x + bv4.x; v.y = c1.x + bv4.y; v.z = c2.x + bv4.z; v.w = c3.x + bv4.w; }
                        else        { v.x = c0.y + bv4.x; v.y = c1.y + bv4.y; v.z = c2.y + bv4.z; v.w = c3.y + bv4.w; }
                        *(float4*)&g_X[off] = v;
                    }
                }
            }
            BARG();   // all X stores for this mt issued by all 4 warps
            if (tid2 == 0) {
                int val = (mt + 1) * 8;
                asm volatile("st.release.cta.b32 [%0], %1;" :: "l"(xprog), "r"(val) : "memory");
            }
        }
    }
}

// =====================================================================
// Kernel 3: emissions (unchanged)
// =====================================================================
__global__ void emis_kernel(const int* __restrict__ lengths,
                            const float* __restrict__ W_out,
                            const float* __restrict__ b_out)
{
    __shared__ float Wsm[KTAG * 2 * HDIM];
    __shared__ float bsm[KTAG];

    const int tid = threadIdx.x;
    for (int i = tid; i < KTAG * 2 * HDIM; i += 256) Wsm[i] = W_out[i];
    if (tid < KTAG) bsm[tid] = b_out[tid];
    __syncthreads();

    const int warp = tid >> 5;
    const int lane = tid & 31;
    const int r = blockIdx.x * 8 + warp;
    const int b = r >> 9;
    const int t = r & 511;
    const int len = lengths[b];
    const int tr  = (t < len) ? (len - 1 - t) : t;
    const int bt = b >> 3, b_l = b & 7;

    const float* hf = g_h + ((size_t)(0 * 8 + bt)) * (TT * 8 * HDIM)
                          + (size_t)t  * (8 * HDIM) + b_l * HDIM;
    const float* hb = g_h + ((size_t)(1 * 8 + bt)) * (TT * 8 * HDIM)
                          + (size_t)tr * (8 * HDIM) + b_l * HDIM;

    float x[16];
#pragma unroll
    for (int i = 0; i < 8; i++) x[i]     = hf[lane + 32 * i];
#pragma unroll
    for (int i = 0; i < 8; i++) x[8 + i] = hb[lane + 32 * i];

    for (int kk = 0; kk < KTAG; kk++) {
        const float* w = Wsm + (size_t)kk * (2 * HDIM);
        float s = 0.f;
#pragma unroll
        for (int i = 0; i < 8; i++) s += x[i]     * w[lane + 32 * i];
#pragma unroll
        for (int i = 0; i < 8; i++) s += x[8 + i] * w[HDIM + lane + 32 * i];
#pragma unroll
        for (int off = 16; off; off >>= 1) s += __shfl_xor_sync(0xffffffffu, s, off);
        if (lane == 0) g_emis[((size_t)b * TT + t) * KTAG + kk] = s + bsm[kk];
    }
}

// =====================================================================
// Kernel 4: Viterbi (unchanged from R8)
// =====================================================================
#define VIT_SMEM 53248
#define VCOMB(av, ai_, bv, bi_) { if ((bv) > (av)) { (av) = (bv); (ai_) = (bi_); } }

__global__ void viterbi_kernel(const int* __restrict__ lengths,
                               const int* __restrict__ stop_id_p,
                               const float* __restrict__ trans,
                               float* __restrict__ out)
{
    extern __shared__ char vsm[];
    float* emis_s = (float*)vsm;
    float* trp    = emis_s + TT * KTAG;
    float* term   = trp + KTAG * 21;
    unsigned char* bp = (unsigned char*)(term + KTAG);

    const int b = blockIdx.x;
    const int lane = threadIdx.x;

    for (int i = lane; i < TT * KTAG; i += 32)
        emis_s[i] = g_emis[(size_t)b * TT * KTAG + i];
    for (int i = lane; i < KTAG * KTAG; i += 32)
        trp[(i / KTAG) * 21 + (i % KTAG)] = trans[i];
    __syncwarp();

    const int len  = lengths[b];
    const int stop = *stop_id_p;
    const float* trl = trp + (lane < KTAG ? lane : 0) * 21;

    float d = 0.f;

    for (int t = 0; t < TT; t++) {
        float em = (lane < KTAG) ? emis_s[t * KTAG + lane] : 0.f;

        float v[KTAG];
#pragma unroll
        for (int p = 0; p < KTAG; p++)
            v[p] = __shfl_sync(0xffffffffu, d, p) + trl[p];

        float w10[10]; int i10[10];
#pragma unroll
        for (int i = 0; i < 10; i++) {
            w10[i] = v[2 * i]; i10[i] = 2 * i;
            VCOMB(w10[i], i10[i], v[2 * i + 1], 2 * i + 1);
        }
        float w5[5]; int i5[5];
#pragma unroll
        for (int i = 0; i < 5; i++) {
            w5[i] = w10[2 * i]; i5[i] = i10[2 * i];
            VCOMB(w5[i], i5[i], w10[2 * i + 1], i10[2 * i + 1]);
        }
        float bv0 = w5[0]; int bi0 = i5[0];
        VCOMB(bv0, bi0, w5[1], i5[1]);
        float bv1 = w5[2]; int bi1 = i5[2];
        VCOMB(bv1, bi1, w5[3], i5[3]);
        VCOMB(bv0, bi0, bv1, bi1);
        VCOMB(bv0, bi0, w5[4], i5[4]);

        bool valid = (t < len);
        if (lane < KTAG) {
            float nd = bv0 + em;
            int bpv  = valid ? bi0 : lane;
            d = valid ? nd : d;
            bp[t * KTAG + lane] = (unsigned char)bpv;
        }
    }

    if (lane < KTAG) term[lane] = d + trp[stop * 21 + lane];
    __syncwarp();

    if (lane == 0) {
        float best = -3.4e38f; int arg = 0;
        for (int j = 0; j < KTAG; j++)
            if (term[j] > best) { best = term[j]; arg = j; }
        out[b] = best;
        float* po = out + BB + (size_t)b * (TT + 1);
        po[TT] = (float)arg;
        int tag = arg;
        for (int t = TT - 1; t >= 0; t--) {
            tag = bp[t * KTAG + tag];
            po[t] = (float)tag;
        }
    }
}

// =====================================================================
// launch
// =====================================================================
extern "C" void kernel_launch(void* const* d_in, const int* in_sizes, int n_in,
                              void* d_out, int out_size)
{
    (void)in_sizes; (void)n_in; (void)out_size;
    const int*   sentence = (const int*)d_in[0];
    const int*   lengths  = (const int*)d_in[1];
    const int*   stop_id  = (const int*)d_in[3];
    const float* emb      = (const float*)d_in[4];
    const float* Wf_ih    = (const float*)d_in[5];
    const float* Wf_hh    = (const float*)d_in[6];
    const float* bf       = (const float*)d_in[7];
    const float* Wb_ih    = (const float*)d_in[8];
    const float* Wb_hh    = (const float*)d_in[9];
    const float* bb       = (const float*)d_in[10];
    const float* W_out    = (const float*)d_in[11];
    const float* b_out    = (const float*)d_in[12];
    const float* trans    = (const float*)d_in[13];
    float* out = (float*)d_out;

    static int attr_set = 0;
    if (!attr_set) {
        cudaFuncSetAttribute(fused_persistent_kernel,
                             cudaFuncAttributeMaxDynamicSharedMemorySize, SMEM_FUSED);
        cudaFuncSetAttribute(viterbi_kernel,
                             cudaFuncAttributeMaxDynamicSharedMemorySize, VIT_SMEM);
        attr_set = 1;
    }

    fused_persistent_kernel<<<GRID_P, 384, SMEM_FUSED>>>(
        sentence, lengths, emb, Wf_ih, bf, Wb_ih, bb, Wf_hh, Wb_hh);

    emis_kernel<<<BB * TT / 8, 256>>>(lengths, W_out, b_out);

    viterbi_kernel<<<BB, 32, VIT_SMEM>>>(lengths, stop_id, trans, out);
}

// round 11
// speedup vs baseline: 1.8550x; 1.0135x over previous
#include <cuda_runtime.h>
#include <math.h>

// Problem constants
#define BB   64
#define TT   512
#define EE   300
#define HDIM 256
#define G4   1024
#define KTAG 20
#define GRID_P 128

typedef unsigned long long ull;

// ---------------- scratch ----------------
// g_X blocked: [dir][bt][ks][t][b_l][gate][k_l]
__device__ float g_X[(size_t)2 * BB * TT * G4];
// g_h blocked: [dir][bt][t][b_l][k]
__device__ float g_h[(size_t)2 * BB * TT * HDIM];
__device__ float g_emis[(size_t)BB * TT * KTAG];
// per-(group, producerCTA, producerWarp) monotone flags, 128B apart
__device__ int   g_flagsB[16 * 8 * 8 * 32];

// ---------------- packed fp32x2 helpers ----------------
__device__ __forceinline__ ull ffma2(ull a, ull b, ull c) {
    ull d;
    asm("fma.rn.f32x2 %0, %1, %2, %3;" : "=l"(d) : "l"(a), "l"(b), "l"(c));
    return d;
}
__device__ __forceinline__ ull f2u2(float x, float y) {
    ull v;
    asm("mov.b64 %0, {%1, %2};" : "=l"(v) : "f"(x), "f"(y));
    return v;
}
__device__ __forceinline__ float2 u2f2(ull v) {
    float2 f;
    asm("mov.b64 {%0, %1}, %2;" : "=f"(f.x), "=f"(f.y) : "l"(v));
    return f;
}

#define BARL() asm volatile("bar.sync 4, 256;" ::: "memory")
#define BARG() asm volatile("bar.sync 5, 128;" ::: "memory")

__device__ __forceinline__ float sigf(float x) { return 1.f / (1.f + expf(-x)); }

// =====================================================================
// FUSED persistent kernel: 128 CTAs x 384 threads.
//   warps 0-3  : gates GEMM (LOW wid -> fills idle issue slots)
//   warps 4-11 : LSTM, warp-decoupled sync:
//     - warp w's dot-product slice needs only h from peer CTA ks==w
//     - per-(CTA,warp) release flags; consumer warp polls 8 flags of
//       its one producer CTA, reloads its warp-PRIVATE hsm slice
//     - ONE bar.sync per step (psum STS->LDS), psum double-buffered
// =====================================================================
#define WP_ULL (4 * 128 * 33)
// Wp 135168 | hsm 8192 | ps 2x32768 | As 4608 | Bs 4352 | tok 256 | xprog 128
#define SMEM_FUSED 218240

__global__ void __launch_bounds__(384, 1)
fused_persistent_kernel(const int* __restrict__ sentence,
                        const int* __restrict__ lengths,
                        const float* __restrict__ emb,
                        const float* __restrict__ Wf_ih,
                        const float* __restrict__ bf,
                        const float* __restrict__ Wb_ih,
                        const float* __restrict__ bb,
                        const float* __restrict__ Wf_hh,
                        const float* __restrict__ Wb_hh)
{
    extern __shared__ char smraw[];
    ull*   Wp   = (ull*)smraw;                   // [4][128][33]
    float* hsm  = (float*)(Wp + WP_ULL);         // [8 warps][128 ull] warp-private h slices
    float* ps   = hsm + 2048;                    // [2][8][4][8][32] double-buffered psum
    float* As   = ps + 16384;                    // [16][72]
    float* Bs   = As + 16 * 72;                  // [16][68]
    int*   tok2 = (int*)(Bs + 16 * 68);          // [64]
    int*   xprog = tok2 + 64;
    ull*   hsmu = (ull*)hsm;

    const int bx  = blockIdx.x;
    const int dir = bx & 1;
    const int ks  = (bx >> 1) & 7;
    const int bt  = bx >> 4;
    const int k0s = ks * 32;
    const int b0  = bt * 8;
    const int tid = threadIdx.x;
    const int grp = bt * 2 + dir;

    const float* __restrict__ Whh  = dir ? Wb_hh : Wf_hh;
    const float* __restrict__ Wih  = dir ? Wb_ih : Wf_ih;
    const float* __restrict__ bias = dir ? bb    : bf;

    // one-time init (all 384 threads)
    for (int i = tid; i < 128 * 128; i += 384) {
        int r = i >> 7;
        int j = i & 127;
        int g = r >> 5, kl = r & 31;
        ull v = *(const ull*)(Whh + (size_t)(g * 256 + k0s + kl) * HDIM + 2 * j);
        Wp[(g * 128 + j) * 33 + kl] = v;
    }
    for (int i = tid; i < 2048; i += 384) hsm[i] = 0.f;   // h(-1)=0
    if (tid == 0) *xprog = 0;
    __syncthreads();

    if (tid >= 128) {
        // ================= LSTM half (warps 4-11, HIGH priority) =========
        const int ltid = tid - 128;
        const int lane = ltid & 31;
        const int warp = ltid >> 5;        // 0..7
        const int b2   = warp;

        // my publish flag: (grp, myCTA=ks, myWarp=warp)
        int* myflag = &g_flagsB[(((grp * 8) + ks) * 8 + warp) * 32];
        // my producers: CTA ks'==warp, all 8 warps
        int* prodflags = &g_flagsB[(((grp * 8) + warp) * 8) * 32];

        const int base = *(volatile int*)myflag;   // all slots equal at launch

        const float* xme = g_X + ((size_t)((dir * 8 + bt) * 8 + ks)) * (TT * 1024)
                               + b2 * 128 + lane;
        const size_t grpH = ((size_t)(dir * 8 + bt)) * (TT * 8 * HDIM);
        float* hme = g_h + grpH + b2 * HDIM + (k0s + lane);
        // reload source: h(t-1), my warp's k-window [warp*32, +32), all 8 b
        const float* hsrc = g_h + grpH + (lane >> 2) * HDIM + warp * 32 + (lane & 3) * 8;
        ull* hdst = hsmu + warp * 128 + (lane >> 2) * 16 + (lane & 3) * 4;

        float c_st = 0.f;

        for (int t = 0; t < TT; t++) {
            if (t > 0) {
                const int target = base + t;
                // poll ONLY my producer CTA's 8 warp-flags
                int fv = 0;
                bool done;
                do {
                    if (lane < 8)
                        asm volatile("ld.acquire.gpu.global.b32 %0, [%1];"
                                     : "=r"(fv) : "l"(prodflags + lane * 32) : "memory");
                    done = __all_sync(0xffffffffu, (lane >= 8) || (fv >= target));
                } while (!done);
                __syncwarp();

                // reload warp-private hsm slice (no barrier needed: private)
                const float* src = hsrc + (size_t)(t - 1) * (8 * HDIM);
                float4 v0 = *(const float4*)src;
                float4 v1 = *(const float4*)(src + 4);
                *(float4*)hdst       = v0;
                *(float4*)(hdst + 2) = v1;
                __syncwarp();
            }

            // wait for this CTA's GEMM warps to have produced X(t)
            int xv;
            do {
                asm volatile("ld.acquire.cta.b32 %0, [%1];" : "=r"(xv) : "l"(xprog) : "memory");
            } while (xv < t + 1);

            const float* xr = xme + (size_t)t * 1024;
            float xi = xr[0], xf = xr[32], xg = xr[64], xo = xr[96];

            // ---- partial dot products over my warp's kk window ----
            ull acc[4][8];
#pragma unroll
            for (int g = 0; g < 4; g++)
#pragma unroll
                for (int b = 0; b < 8; b++) acc[g][b] = 0ull;

            const ull* hW = hsmu + warp * 128;
            const int kkb = warp * 16;
#pragma unroll 4
            for (int c = 0; c < 16; c++) {
                int kk2 = kkb + c;
                ull w0 = Wp[(0 * 128 + kk2) * 33 + lane];
                ull w1 = Wp[(1 * 128 + kk2) * 33 + lane];
                ull w2 = Wp[(2 * 128 + kk2) * 33 + lane];
                ull w3 = Wp[(3 * 128 + kk2) * 33 + lane];
#pragma unroll
                for (int b = 0; b < 8; b++) {
                    ull h2 = hW[b * 16 + c];   // warp-uniform broadcast
                    acc[0][b] = ffma2(h2, w0, acc[0][b]);
                    acc[1][b] = ffma2(h2, w1, acc[1][b]);
                    acc[2][b] = ffma2(h2, w2, acc[2][b]);
                    acc[3][b] = ffma2(h2, w3, acc[3][b]);
                }
            }

            float* pb = ps + (t & 1) * 8192;
#pragma unroll
            for (int g = 0; g < 4; g++)
#pragma unroll
                for (int b = 0; b < 8; b++) {
                    float2 s = u2f2(acc[g][b]);
                    pb[((warp * 4 + g) * 8 + b) * 32 + lane] = s.x + s.y;
                }
            BARL();   // the ONLY per-step block barrier

            float s0 = 0.f, s1 = 0.f, s2 = 0.f, s3 = 0.f;
#pragma unroll
            for (int w = 0; w < 8; w++) {
                s0 += pb[((w * 4 + 0) * 8 + b2) * 32 + lane];
                s1 += pb[((w * 4 + 1) * 8 + b2) * 32 + lane];
                s2 += pb[((w * 4 + 2) * 8 + b2) * 32 + lane];
                s3 += pb[((w * 4 + 3) * 8 + b2) * 32 + lane];
            }
            float gi = xi + s0;
            float gf = xf + s1;
            float gg = xg + s2;
            float go = xo + s3;

            c_st = sigf(gf) * c_st + sigf(gi) * tanhf(gg);
            float hn = sigf(go) * tanhf(c_st);
            hme[(size_t)t * (8 * HDIM)] = hn;          // publish h(t)

            if (t + 1 < TT) {
                __syncwarp();                          // order warp's h stores
                if (lane == 0)
                    asm volatile("st.release.gpu.global.b32 [%0], %1;"
                                 :: "l"(myflag), "r"(base + t + 1) : "memory");
            }
        }
    } else {
        // ================= GEMM half (warps 0-3, LOW priority) ===========
        const int tid2 = tid;
        const int tx = tid2 & 15;
        const int ty = tid2 >> 4;
        const int nl = tid2 >> 1;
        const int kc = (tid2 & 1) * 8;
        const size_t xbase = ((size_t)((dir * 8 + bt) * 8 + ks)) * (TT * 1024);

        for (int mt = 0; mt < 64; mt++) {
            if (tid2 < 64) {
                int tloc = tid2 >> 3, b_l = tid2 & 7;
                int t = mt * 8 + tloc, b = b0 + b_l;
                int tt = t;
                if (dir) { int len = lengths[b]; tt = (t < len) ? (len - 1 - t) : t; }
                tok2[tid2] = sentence[b * TT + tt];
            }
            BARG();

            for (int nt = 0; nt < 2; nt++) {
                ull acc[4][4];
#pragma unroll
                for (int i = 0; i < 4; i++)
#pragma unroll
                    for (int j = 0; j < 4; j++) acc[i][j] = 0ull;

                const int nglob = nt * 64 + nl;
                const float* wrow = Wih + (size_t)((nglob >> 5) * 256 + k0s + (nglob & 31)) * EE;
                const float* erow = emb + (size_t)tok2[nl] * EE;

                for (int k0 = 0; k0 < 304; k0 += 16) {
                    const int kb = k0 + kc;
                    if (kb + 8 <= EE) {
                        float4 v0 = *(const float4*)(erow + kb);
                        float4 v1 = *(const float4*)(erow + kb + 4);
                        As[(kc + 0) * 72 + nl] = v0.x;
                        As[(kc + 1) * 72 + nl] = v0.y;
                        As[(kc + 2) * 72 + nl] = v0.z;
                        As[(kc + 3) * 72 + nl] = v0.w;
                        As[(kc + 4) * 72 + nl] = v1.x;
                        As[(kc + 5) * 72 + nl] = v1.y;
                        As[(kc + 6) * 72 + nl] = v1.z;
                        As[(kc + 7) * 72 + nl] = v1.w;
                    } else {
#pragma unroll
                        for (int i = 0; i < 8; i++)
                            As[(kc + i) * 72 + nl] = (kb + i < EE) ? erow[kb + i] : 0.f;
                    }
                    if (kb + 8 <= EE) {
                        float4 v0 = *(const float4*)(wrow + kb);
                        float4 v1 = *(const float4*)(wrow + kb + 4);
                        Bs[(kc + 0) * 68 + nl] = v0.x;
                        Bs[(kc + 1) * 68 + nl] = v0.y;
                        Bs[(kc + 2) * 68 + nl] = v0.z;
                        Bs[(kc + 3) * 68 + nl] = v0.w;
                        Bs[(kc + 4) * 68 + nl] = v1.x;
                        Bs[(kc + 5) * 68 + nl] = v1.y;
                        Bs[(kc + 6) * 68 + nl] = v1.z;
                        Bs[(kc + 7) * 68 + nl] = v1.w;
                    } else {
#pragma unroll
                        for (int i = 0; i < 8; i++)
                            Bs[(kc + i) * 68 + nl] = (kb + i < EE) ? wrow[kb + i] : 0.f;
                    }
                    BARG();

#pragma unroll
                    for (int kk = 0; kk < 16; kk++) {
                        ulonglong2 a0 = *(const ulonglong2*)&As[kk * 72 + ty * 8];
                        ulonglong2 a1 = *(const ulonglong2*)&As[kk * 72 + ty * 8 + 4];
                        float4 bv = *(const float4*)&Bs[kk * 68 + tx * 4];
                        ull q0 = f2u2(bv.x, bv.x);
                        ull q1 = f2u2(bv.y, bv.y);
                        ull q2 = f2u2(bv.z, bv.z);
                        ull q3 = f2u2(bv.w, bv.w);
                        acc[0][0] = ffma2(a0.x, q0, acc[0][0]);
                        acc[0][1] = ffma2(a0.x, q1, acc[0][1]);
                        acc[0][2] = ffma2(a0.x, q2, acc[0][2]);
                        acc[0][3] = ffma2(a0.x, q3, acc[0][3]);
                        acc[1][0] = ffma2(a0.y, q0, acc[1][0]);
                        acc[1][1] = ffma2(a0.y, q1, acc[1][1]);
                        acc[1][2] = ffma2(a0.y, q2, acc[1][2]);
                        acc[1][3] = ffma2(a0.y, q3, acc[1][3]);
                        acc[2][0] = ffma2(a1.x, q0, acc[2][0]);
                        acc[2][1] = ffma2(a1.x, q1, acc[2][1]);
                        acc[2][2] = ffma2(a1.x, q2, acc[2][2]);
                        acc[2][3] = ffma2(a1.x, q3, acc[2][3]);
                        acc[3][0] = ffma2(a1.y, q0, acc[3][0]);
                        acc[3][1] = ffma2(a1.y, q1, acc[3][1]);
                        acc[3][2] = ffma2(a1.y, q2, acc[3][2]);
                        acc[3][3] = ffma2(a1.y, q3, acc[3][3]);
                    }
                    BARG();
                }

                const int ng = nt * 64 + tx * 4;
                const float* bp2 = bias + (ng >> 5) * 256 + k0s + (ng & 31);
                float4 bv4;
                bv4.x = bp2[0]; bv4.y = bp2[1]; bv4.z = bp2[2]; bv4.w = bp2[3];
#pragma unroll
                for (int mp = 0; mp < 4; mp++) {
                    float2 c0 = u2f2(acc[mp][0]);
                    float2 c1 = u2f2(acc[mp][1]);
                    float2 c2 = u2f2(acc[mp][2]);
                    float2 c3 = u2f2(acc[mp][3]);
#pragma unroll
                    for (int h = 0; h < 2; h++) {
                        int m = ty * 8 + 2 * mp + h;
                        int tloc = m >> 3, b_l = m & 7;
                        size_t off = xbase + (size_t)(mt * 8 + tloc) * 1024 + b_l * 128 + ng;
                        float4 v;
                        if (h == 0) { v.x = c0.x + bv4.x; v.y = c1.x + bv4.y; v.z = c2.x + bv4.z; v.w = c3.x + bv4.w; }
                        else        { v.x = c0.y + bv4.x; v.y = c1.y + bv4.y; v.z = c2.y + bv4.z; v.w = c3.y + bv4.w; }
                        *(float4*)&g_X[off] = v;
                    }
                }
            }
            BARG();
            if (tid2 == 0) {
                int val = (mt + 1) * 8;
                asm volatile("st.release.cta.b32 [%0], %1;" :: "l"(xprog), "r"(val) : "memory");
            }
        }
    }
}

// =====================================================================
// Kernel 3: emissions (unchanged)
// =====================================================================
__global__ void emis_kernel(const int* __restrict__ lengths,
                            const float* __restrict__ W_out,
                            const float* __restrict__ b_out)
{
    __shared__ float Wsm[KTAG * 2 * HDIM];
    __shared__ float bsm[KTAG];

    const int tid = threadIdx.x;
    for (int i = tid; i < KTAG * 2 * HDIM; i += 256) Wsm[i] = W_out[i];
    if (tid < KTAG) bsm[tid] = b_out[tid];
    __syncthreads();

    const int warp = tid >> 5;
    const int lane = tid & 31;
    const int r = blockIdx.x * 8 + warp;
    const int b = r >> 9;
    const int t = r & 511;
    const int len = lengths[b];
    const int tr  = (t < len) ? (len - 1 - t) : t;
    const int bt = b >> 3, b_l = b & 7;

    const float* hf = g_h + ((size_t)(0 * 8 + bt)) * (TT * 8 * HDIM)
                          + (size_t)t  * (8 * HDIM) + b_l * HDIM;
    const float* hb = g_h + ((size_t)(1 * 8 + bt)) * (TT * 8 * HDIM)
                          + (size_t)tr * (8 * HDIM) + b_l * HDIM;

    float x[16];
#pragma unroll
    for (int i = 0; i < 8; i++) x[i]     = hf[lane + 32 * i];
#pragma unroll
    for (int i = 0; i < 8; i++) x[8 + i] = hb[lane + 32 * i];

    for (int kk = 0; kk < KTAG; kk++) {
        const float* w = Wsm + (size_t)kk * (2 * HDIM);
        float s = 0.f;
#pragma unroll
        for (int i = 0; i < 8; i++) s += x[i]     * w[lane + 32 * i];
#pragma unroll
        for (int i = 0; i < 8; i++) s += x[8 + i] * w[HDIM + lane + 32 * i];
#pragma unroll
        for (int off = 16; off; off >>= 1) s += __shfl_xor_sync(0xffffffffu, s, off);
        if (lane == 0) g_emis[((size_t)b * TT + t) * KTAG + kk] = s + bsm[kk];
    }
}

// =====================================================================
// Kernel 4: Viterbi (unchanged from R8/R10)
// =====================================================================
#define VIT_SMEM 53248
#define VCOMB(av, ai_, bv, bi_) { if ((bv) > (av)) { (av) = (bv); (ai_) = (bi_); } }

__global__ void viterbi_kernel(const int* __restrict__ lengths,
                               const int* __restrict__ stop_id_p,
                               const float* __restrict__ trans,
                               float* __restrict__ out)
{
    extern __shared__ char vsm[];
    float* emis_s = (float*)vsm;
    float* trp    = emis_s + TT * KTAG;
    float* term   = trp + KTAG * 21;
    unsigned char* bp = (unsigned char*)(term + KTAG);

    const int b = blockIdx.x;
    const int lane = threadIdx.x;

    for (int i = lane; i < TT * KTAG; i += 32)
        emis_s[i] = g_emis[(size_t)b * TT * KTAG + i];
    for (int i = lane; i < KTAG * KTAG; i += 32)
        trp[(i / KTAG) * 21 + (i % KTAG)] = trans[i];
    __syncwarp();

    const int len  = lengths[b];
    const int stop = *stop_id_p;
    const float* trl = trp + (lane < KTAG ? lane : 0) * 21;

    float d = 0.f;

    for (int t = 0; t < TT; t++) {
        float em = (lane < KTAG) ? emis_s[t * KTAG + lane] : 0.f;

        float v[KTAG];
#pragma unroll
        for (int p = 0; p < KTAG; p++)
            v[p] = __shfl_sync(0xffffffffu, d, p) + trl[p];

        float w10[10]; int i10[10];
#pragma unroll
        for (int i = 0; i < 10; i++) {
            w10[i] = v[2 * i]; i10[i] = 2 * i;
            VCOMB(w10[i], i10[i], v[2 * i + 1], 2 * i + 1);
        }
        float w5[5]; int i5[5];
#pragma unroll
        for (int i = 0; i < 5; i++) {
            w5[i] = w10[2 * i]; i5[i] = i10[2 * i];
            VCOMB(w5[i], i5[i], w10[2 * i + 1], i10[2 * i + 1]);
        }
        float bv0 = w5[0]; int bi0 = i5[0];
        VCOMB(bv0, bi0, w5[1], i5[1]);
        float bv1 = w5[2]; int bi1 = i5[2];
        VCOMB(bv1, bi1, w5[3], i5[3]);
        VCOMB(bv0, bi0, bv1, bi1);
        VCOMB(bv0, bi0, w5[4], i5[4]);

        bool valid = (t < len);
        if (lane < KTAG) {
            float nd = bv0 + em;
            int bpv  = valid ? bi0 : lane;
            d = valid ? nd : d;
            bp[t * KTAG + lane] = (unsigned char)bpv;
        }
    }

    if (lane < KTAG) term[lane] = d + trp[stop * 21 + lane];
    __syncwarp();

    if (lane == 0) {
        float best = -3.4e38f; int arg = 0;
        for (int j = 0; j < KTAG; j++)
            if (term[j] > best) { best = term[j]; arg = j; }
        out[b] = best;
        float* po = out + BB + (size_t)b * (TT + 1);
        po[TT] = (float)arg;
        int tag = arg;
        for (int t = TT - 1; t >= 0; t--) {
            tag = bp[t * KTAG + tag];
            po[t] = (float)tag;
        }
    }
}

// =====================================================================
// launch
// =====================================================================
extern "C" void kernel_launch(void* const* d_in, const int* in_sizes, int n_in,
                              void* d_out, int out_size)
{
    (void)in_sizes; (void)n_in; (void)out_size;
    const int*   sentence = (const int*)d_in[0];
    const int*   lengths  = (const int*)d_in[1];
    const int*   stop_id  = (const int*)d_in[3];
    const float* emb      = (const float*)d_in[4];
    const float* Wf_ih    = (const float*)d_in[5];
    const float* Wf_hh    = (const float*)d_in[6];
    const float* bf       = (const float*)d_in[7];
    const float* Wb_ih    = (const float*)d_in[8];
    const float* Wb_hh    = (const float*)d_in[9];
    const float* bb       = (const float*)d_in[10];
    const float* W_out    = (const float*)d_in[11];
    const float* b_out    = (const float*)d_in[12];
    const float* trans    = (const float*)d_in[13];
    float* out = (float*)d_out;

    static int attr_set = 0;
    if (!attr_set) {
        cudaFuncSetAttribute(fused_persistent_kernel,
                             cudaFuncAttributeMaxDynamicSharedMemorySize, SMEM_FUSED);
        cudaFuncSetAttribute(viterbi_kernel,
                             cudaFuncAttributeMaxDynamicSharedMemorySize, VIT_SMEM);
        attr_set = 1;
    }

    fused_persistent_kernel<<<GRID_P, 384, SMEM_FUSED>>>(
        sentence, lengths, emb, Wf_ih, bf, Wb_ih, bb, Wf_hh, Wb_hh);

    emis_kernel<<<BB * TT / 8, 256>>>(lengths, W_out, b_out);

    viterbi_kernel<<<BB, 32, VIT_SMEM>>>(lengths, stop_id, trans, out);
}